// round 2
// baseline (speedup 1.0000x reference)
#include <cuda_runtime.h>
#include <cstdint>

// Problem constants
#define SEQB   4096          // S*B tokens
#define DIMX   1024
#define NBLK   8
#define BLKD   128
#define NHEAD  12
#define HDIM   64
#define INNER  768           // NHEAD*HDIM
#define QKVW   (NBLK*BLKD*INNER)   // 786432 (also == Wf size)
#define QKVROW (NBLK*INNER)        // 6144
#define SCALE  0.125f              // HEAD_DIM^-0.5

// ---------------- scratch (device globals; no allocation allowed) ----------------
__device__ float g_xr[SEQB*DIMX];        // rna-rounded x           (16 MB)
__device__ float g_wq[QKVW];
__device__ float g_wk[QKVW];
__device__ float g_wv[QKVW];
__device__ float g_wf[QKVW];
__device__ float g_q [SEQB*QKVROW];      // (token, blk, h*64+d)    (100 MB)
__device__ float g_k [SEQB*QKVROW];
__device__ float g_v [SEQB*QKVROW];
__device__ float g_att[SEQB*QKVROW];     // attention out, rna-rounded

// ---------------- helpers ----------------
__device__ __forceinline__ float rna_tf32(float x) {
    uint32_t r;
    asm("cvt.rna.tf32.f32 %0, %1;" : "=r"(r) : "f"(x));
    return __uint_as_float(r);
}

__device__ __forceinline__ void mma_tf32(float c[4],
                                         uint32_t a0, uint32_t a1, uint32_t a2, uint32_t a3,
                                         uint32_t b0, uint32_t b1) {
    asm volatile(
        "mma.sync.aligned.m16n8k8.row.col.f32.tf32.tf32.f32 "
        "{%0,%1,%2,%3}, {%4,%5,%6,%7}, {%8,%9}, {%0,%1,%2,%3};\n"
        : "+f"(c[0]), "+f"(c[1]), "+f"(c[2]), "+f"(c[3])
        : "r"(a0), "r"(a1), "r"(a2), "r"(a3), "r"(b0), "r"(b1));
}

// ---------------- prep: rna-round inputs into scratch ----------------
__global__ void prep_round_kernel(const float* __restrict__ x,
                                  const float* __restrict__ wq,
                                  const float* __restrict__ wk,
                                  const float* __restrict__ wv,
                                  const float* __restrict__ wf) {
    const int n_x = SEQB * DIMX;
    const int n_tot = n_x + 4 * QKVW;
    for (int i = blockIdx.x * blockDim.x + threadIdx.x; i < n_tot;
         i += gridDim.x * blockDim.x) {
        if (i < n_x) {
            g_xr[i] = rna_tf32(x[i]);
        } else {
            int j = i - n_x;
            int seg = j / QKVW;
            int o = j % QKVW;
            if      (seg == 0) g_wq[o] = rna_tf32(wq[o]);
            else if (seg == 1) g_wk[o] = rna_tf32(wk[o]);
            else if (seg == 2) g_wv[o] = rna_tf32(wv[o]);
            else               g_wf[o] = rna_tf32(wf[o]);
        }
    }
}

// ---------------- shared GEMM tile body ----------------
// CTA tile: 128(M) x 64(N), K-step 32. 256 threads = 8 warps in 4(M) x 2(N).
// Each warp computes 32x32 via 2 m-tiles x 4 n-tiles of m16n8k8 tf32 mma.
__device__ __forceinline__ void gemm_tile(const float* __restrict__ A, int lda,
                                          const float* __restrict__ B, int ldb,
                                          float* __restrict__ C, int ldc, int K) {
    __shared__ float As[128][36];   // pad 36: conflict-free A frag reads, 16B aligned
    __shared__ float Bs[32][68];

    const int tid  = threadIdx.x;
    const int lane = tid & 31;
    const int warp = tid >> 5;
    const int wm = warp & 3;        // 0..3 (M)
    const int wn = warp >> 2;       // 0..1 (N)
    const int gid = lane >> 2;      // 0..7
    const int tig = lane & 3;       // 0..3

    float acc[2][4][4];
#pragma unroll
    for (int mt = 0; mt < 2; mt++)
#pragma unroll
        for (int nt = 0; nt < 4; nt++)
#pragma unroll
            for (int e = 0; e < 4; e++) acc[mt][nt][e] = 0.f;

    for (int kt = 0; kt < K; kt += 32) {
        // load A tile 128x32 (float4, fully coalesced)
#pragma unroll
        for (int p = 0; p < 4; p++) {
            int r = (tid >> 3) + p * 32;
            int c = (tid & 7) * 4;
            float4 val = *(const float4*)(A + r * lda + kt + c);
            *(float4*)(&As[r][c]) = val;
        }
        // load B tile 32x64
#pragma unroll
        for (int p = 0; p < 2; p++) {
            int r = (tid >> 4) + p * 16;
            int c = (tid & 15) * 4;
            float4 val = *(const float4*)(B + (kt + r) * ldb + c);
            *(float4*)(&Bs[r][c]) = val;
        }
        __syncthreads();

#pragma unroll
        for (int ks = 0; ks < 4; ks++) {
            const int kk = ks * 8;
            uint32_t a[2][4];
#pragma unroll
            for (int mt = 0; mt < 2; mt++) {
                int r = wm * 32 + mt * 16 + gid;
                a[mt][0] = __float_as_uint(As[r    ][kk + tig    ]);
                a[mt][1] = __float_as_uint(As[r + 8][kk + tig    ]);
                a[mt][2] = __float_as_uint(As[r    ][kk + tig + 4]);
                a[mt][3] = __float_as_uint(As[r + 8][kk + tig + 4]);
            }
#pragma unroll
            for (int nt = 0; nt < 4; nt++) {
                int cn = wn * 32 + nt * 8 + gid;
                uint32_t b0 = __float_as_uint(Bs[kk + tig    ][cn]);
                uint32_t b1 = __float_as_uint(Bs[kk + tig + 4][cn]);
#pragma unroll
                for (int mt = 0; mt < 2; mt++)
                    mma_tf32(acc[mt][nt], a[mt][0], a[mt][1], a[mt][2], a[mt][3], b0, b1);
            }
        }
        __syncthreads();
    }

    // epilogue: float2 stores
#pragma unroll
    for (int mt = 0; mt < 2; mt++) {
#pragma unroll
        for (int nt = 0; nt < 4; nt++) {
            int r  = wm * 32 + mt * 16 + gid;
            int cn = wn * 32 + nt * 8 + tig * 2;
            float2 v0 = make_float2(acc[mt][nt][0], acc[mt][nt][1]);
            float2 v1 = make_float2(acc[mt][nt][2], acc[mt][nt][3]);
            *(float2*)(C + r * ldc + cn)       = v0;
            *(float2*)(C + (r + 8) * ldc + cn) = v1;
        }
    }
}

// ---------------- QKV grouped GEMM: grid (12, 32, 24) ----------------
__global__ void __launch_bounds__(256) gemm_qkv_kernel() {
    const int z   = blockIdx.z;
    const int mat = z >> 3;     // 0=q 1=k 2=v
    const int blk = z & 7;
    const float* W = (mat == 0) ? g_wq : (mat == 1) ? g_wk : g_wv;
    float*       O = (mat == 0) ? g_q  : (mat == 1) ? g_k  : g_v;

    const float* A = g_xr + (size_t)blockIdx.y * 128 * DIMX + blk * BLKD;
    const float* B = W + (size_t)blk * BLKD * INNER + blockIdx.x * 64;
    float*       C = O + (size_t)blockIdx.y * 128 * QKVROW + blk * INNER + blockIdx.x * 64;
    gemm_tile(A, DIMX, B, INNER, C, QKVROW, BLKD);
}

// ---------------- output projection: grid (2, 32, 8) ----------------
__global__ void __launch_bounds__(256) gemm_f_kernel(float* __restrict__ out) {
    const int blk = blockIdx.z;
    const float* A = g_att + (size_t)blockIdx.y * 128 * QKVROW + blk * INNER;
    const float* B = g_wf + (size_t)blk * INNER * BLKD + blockIdx.x * 64;
    float*       C = out + (size_t)blockIdx.y * 128 * DIMX + blk * BLKD + blockIdx.x * 64;
    gemm_tile(A, QKVROW, B, BLKD, C, DIMX, INNER);
}

// ---------------- attention: 1 CTA per token, 1 warp per head ----------------
__global__ void __launch_bounds__(384) attn_kernel(float* __restrict__ smean) {
    const int t    = blockIdx.x;
    const int h    = threadIdx.x >> 5;    // head 0..11
    const int lane = threadIdx.x & 31;

    __shared__ float sm[NHEAD][64];

    const size_t base = (size_t)t * QKVROW + h * HDIM;
    float2 q[8], k[8], v[8];
#pragma unroll
    for (int j = 0; j < 8; j++) {
        q[j] = ((const float2*)(g_q + base + j * INNER))[lane];
        k[j] = ((const float2*)(g_k + base + j * INNER))[lane];
        v[j] = ((const float2*)(g_v + base + j * INNER))[lane];
    }

    // scores: s(i,j) = SCALE * dot64(q_i, k_j); lane owns flat=lane and flat=lane+32
    float own0 = 0.f, own1 = 0.f;
#pragma unroll
    for (int i = 0; i < 8; i++) {
#pragma unroll
        for (int j = 0; j < 8; j++) {
            float p = q[i].x * k[j].x + q[i].y * k[j].y;
#pragma unroll
            for (int m = 16; m > 0; m >>= 1)
                p += __shfl_xor_sync(0xFFFFFFFFu, p, m);
            const int f = i * 8 + j;
            if (f < 32) { if (lane == f)        own0 = p; }
            else        { if (lane == (f & 31)) own1 = p; }
        }
    }
    own0 *= SCALE;
    own1 *= SCALE;

    // softmax over j within 8-lane groups
    float m0 = own0, m1 = own1;
#pragma unroll
    for (int m = 4; m >= 1; m >>= 1) {
        m0 = fmaxf(m0, __shfl_xor_sync(0xFFFFFFFFu, m0, m));
        m1 = fmaxf(m1, __shfl_xor_sync(0xFFFFFFFFu, m1, m));
    }
    float e0 = expf(own0 - m0), e1 = expf(own1 - m1);
    float s0 = e0, s1 = e1;
#pragma unroll
    for (int m = 4; m >= 1; m >>= 1) {
        s0 += __shfl_xor_sync(0xFFFFFFFFu, s0, m);
        s1 += __shfl_xor_sync(0xFFFFFFFFu, s1, m);
    }
    const float a0 = e0 / s0;
    const float a1 = e1 / s1;

    // per-head attn into smem (deterministic head reduction)
    sm[h][lane]      = a0;
    sm[h][lane + 32] = a1;

    // out_i = sum_j a(i,j) * v_j
    float2 acc[8];
#pragma unroll
    for (int i = 0; i < 8; i++) acc[i] = make_float2(0.f, 0.f);
#pragma unroll
    for (int i = 0; i < 8; i++) {
#pragma unroll
        for (int j = 0; j < 8; j++) {
            const int f = i * 8 + j;
            float aij = __shfl_sync(0xFFFFFFFFu, (f < 32) ? a0 : a1, f & 31);
            acc[i].x = fmaf(aij, v[j].x, acc[i].x);
            acc[i].y = fmaf(aij, v[j].y, acc[i].y);
        }
    }
#pragma unroll
    for (int i = 0; i < 8; i++) {
        float2 o = make_float2(rna_tf32(acc[i].x), rna_tf32(acc[i].y));
        *(float2*)(g_att + (size_t)t * QKVROW + i * INNER + h * HDIM + 2 * lane) = o;
    }

    __syncthreads();
    // score_mean over heads -> (t, i, j)
    if (smean != nullptr && threadIdx.x < 64) {
        float s = 0.f;
#pragma unroll
        for (int hh = 0; hh < NHEAD; hh++) s += sm[hh][threadIdx.x];
        smean[(size_t)t * 64 + threadIdx.x] = s * (1.0f / 12.0f);
    }
}

// ---------------- launch ----------------
extern "C" void kernel_launch(void* const* d_in, const int* in_sizes, int n_in,
                              void* d_out, int out_size) {
    const float* x  = (const float*)d_in[0];
    const float* Wq = (const float*)d_in[1];
    const float* Wk = (const float*)d_in[2];
    const float* Wv = (const float*)d_in[3];
    const float* Wf = (const float*)d_in[4];
    float* out = (float*)d_out;

    prep_round_kernel<<<2048, 256>>>(x, Wq, Wk, Wv, Wf);

    gemm_qkv_kernel<<<dim3(12, 32, 24), 256>>>();

    float* smean = (out_size >= SEQB * DIMX + SEQB * 64) ? (out + (size_t)SEQB * DIMX)
                                                         : nullptr;
    attn_kernel<<<SEQB, 384>>>(smean);

    gemm_f_kernel<<<dim3(2, 32, 8), 256>>>(out);
}

// round 3
// speedup vs baseline: 1.5813x; 1.5813x over previous
#include <cuda_runtime.h>
#include <cuda_fp16.h>
#include <cstdint>

// Problem constants
#define SEQB   4096
#define DIMX   1024
#define NBLK   8
#define BLKD   128
#define NHEAD  12
#define HDIM   64
#define INNER  768
#define QKVROW (NBLK*INNER)        // 6144
#define WELEM  (NBLK*BLKD*INNER)   // 786432
#define SCALE  0.125f
#define AST    40                  // smem row stride in halves (80B, conflict-free frags)

// ---------------- scratch (device globals; allocation is forbidden) ----------------
__device__ __align__(16) __half g_xh [SEQB*DIMX];     // x rounded to half
__device__ __align__(16) __half g_wqt[WELEM];         // [blk][n=INNER][k=BLKD]
__device__ __align__(16) __half g_wkt[WELEM];
__device__ __align__(16) __half g_wvt[WELEM];
__device__ __align__(16) __half g_wft[WELEM];         // [blk][n=BLKD][k=INNER]
__device__ __align__(16) __half g_q  [SEQB*QKVROW];
__device__ __align__(16) __half g_k  [SEQB*QKVROW];
__device__ __align__(16) __half g_v  [SEQB*QKVROW];
__device__ __align__(16) __half g_att[SEQB*QKVROW];

// ---------------- helpers ----------------
__device__ __forceinline__ void mma_f16(float c[4], const uint32_t a[4],
                                        uint32_t b0, uint32_t b1) {
    asm volatile(
        "mma.sync.aligned.m16n8k16.row.col.f32.f16.f16.f32 "
        "{%0,%1,%2,%3}, {%4,%5,%6,%7}, {%8,%9}, {%0,%1,%2,%3};\n"
        : "+f"(c[0]), "+f"(c[1]), "+f"(c[2]), "+f"(c[3])
        : "r"(a[0]), "r"(a[1]), "r"(a[2]), "r"(a[3]), "r"(b0), "r"(b1));
}

__device__ __forceinline__ void cp_async16(const __half* smem_dst, const __half* gmem_src) {
    uint32_t sa = (uint32_t)__cvta_generic_to_shared((void*)smem_dst);
    asm volatile("cp.async.ca.shared.global [%0], [%1], 16;\n" :: "r"(sa), "l"(gmem_src));
}
__device__ __forceinline__ void cp_commit() { asm volatile("cp.async.commit_group;\n"); }
__device__ __forceinline__ void cp_wait1()  { asm volatile("cp.async.wait_group 1;\n"); }
__device__ __forceinline__ void cp_wait0()  { asm volatile("cp.async.wait_group 0;\n"); }

// ---------------- prep: x -> half ----------------
__global__ void conv_x_kernel(const float* __restrict__ x) {
    int i = (blockIdx.x * blockDim.x + threadIdx.x) * 4;
    float4 v = *(const float4*)(x + i);
    __half2* o = (__half2*)(g_xh + i);
    o[0] = __floats2half2_rn(v.x, v.y);
    o[1] = __floats2half2_rn(v.z, v.w);
}

// ---------------- prep: transpose weights to [blk][n][k] half ----------------
// grid.z selects (mat, blk); grid.x tiles dout(n), grid.y tiles din(k). 256 threads.
__global__ void transpose_qkv_kernel(const float* __restrict__ wq,
                                     const float* __restrict__ wk,
                                     const float* __restrict__ wv) {
    __shared__ float tile[32][33];
    const int mat = blockIdx.z >> 3;
    const int blk = blockIdx.z & 7;
    const float* W = (mat == 0) ? wq : (mat == 1) ? wk : wv;
    __half* O      = (mat == 0) ? g_wqt : (mat == 1) ? g_wkt : g_wvt;
    const float* Wb = W + (size_t)blk * BLKD * INNER;   // [k=BLKD][n=INNER]
    __half* Ob      = O + (size_t)blk * BLKD * INNER;   // [n=INNER][k=BLKD]
    int n0 = blockIdx.x * 32, k0 = blockIdx.y * 32;
    int tx = threadIdx.x & 31, ty0 = threadIdx.x >> 5;
#pragma unroll
    for (int p = 0; p < 4; p++) {
        int ty = ty0 + p * 8;
        tile[ty][tx] = Wb[(size_t)(k0 + ty) * INNER + n0 + tx];
    }
    __syncthreads();
#pragma unroll
    for (int p = 0; p < 4; p++) {
        int ty = ty0 + p * 8;
        Ob[(size_t)(n0 + ty) * BLKD + k0 + tx] = __float2half_rn(tile[tx][ty]);
    }
}

__global__ void transpose_f_kernel(const float* __restrict__ wf) {
    __shared__ float tile[32][33];
    const int blk = blockIdx.z;
    const float* Wb = wf + (size_t)blk * INNER * BLKD;  // [k=INNER][n=BLKD]
    __half* Ob      = g_wft + (size_t)blk * INNER * BLKD; // [n=BLKD][k=INNER]
    int n0 = blockIdx.x * 32, k0 = blockIdx.y * 32;
    int tx = threadIdx.x & 31, ty0 = threadIdx.x >> 5;
#pragma unroll
    for (int p = 0; p < 4; p++) {
        int ty = ty0 + p * 8;
        tile[ty][tx] = Wb[(size_t)(k0 + ty) * BLKD + n0 + tx];
    }
    __syncthreads();
#pragma unroll
    for (int p = 0; p < 4; p++) {
        int ty = ty0 + p * 8;
        Ob[(size_t)(n0 + ty) * INNER + k0 + tx] = __float2half_rn(tile[tx][ty]);
    }
}

// ---------------- GEMM tile body: 128(M) x 64(N), K-step 32, double-buffered ----------
// 256 threads, 8 warps 4(M)x2(N); warp = 32x32 via 2mt x 4nt of m16n8k16.
// A row-major [m][k] half, B transposed [n][k] half, C row-major.
template <bool HALF_OUT>
__device__ __forceinline__ void gemm_body(const __half* __restrict__ A, int lda,
                                          const __half* __restrict__ B, int ldb,
                                          void* __restrict__ C, int ldc, int K) {
    __shared__ __half As[2][128 * AST];
    __shared__ __half Bs[2][64 * AST];

    const int tid  = threadIdx.x;
    const int lane = tid & 31;
    const int warp = tid >> 5;
    const int wm = warp & 3, wn = warp >> 2;
    const int gid = lane >> 2, tig = lane & 3;

    float acc[2][4][4];
#pragma unroll
    for (int mt = 0; mt < 2; mt++)
#pragma unroll
        for (int nt = 0; nt < 4; nt++)
#pragma unroll
            for (int e = 0; e < 4; e++) acc[mt][nt][e] = 0.f;

    // stage loader: As 128x32 halves (512 x 16B chunks), Bs 64x32 (256 chunks)
    const int ar0 = tid >> 2,        ac0 = (tid & 3) * 8;
    const int ar1 = (tid + 256) >> 2;
    const int br  = tid >> 2,        bc  = (tid & 3) * 8;

#define LOAD_STAGE(st, kt)                                                      \
    do {                                                                        \
        cp_async16(&As[st][ar0 * AST + ac0], A + (size_t)ar0 * lda + (kt) + ac0); \
        cp_async16(&As[st][ar1 * AST + ac0], A + (size_t)ar1 * lda + (kt) + ac0); \
        cp_async16(&Bs[st][br  * AST + bc ], B + (size_t)br  * ldb + (kt) + bc ); \
        cp_commit();                                                            \
    } while (0)

    const int nK = K / 32;
    LOAD_STAGE(0, 0);

    for (int t = 0; t < nK; t++) {
        if (t + 1 < nK) { LOAD_STAGE((t + 1) & 1, (t + 1) * 32); cp_wait1(); }
        else            { cp_wait0(); }
        __syncthreads();

        const __half* as = As[t & 1];
        const __half* bs = Bs[t & 1];
#pragma unroll
        for (int ks = 0; ks < 2; ks++) {
            const int kk = ks * 16;
            uint32_t a[2][4];
#pragma unroll
            for (int mt = 0; mt < 2; mt++) {
                const __half* ap = as + (wm * 32 + mt * 16 + gid) * AST + kk + tig * 2;
                a[mt][0] = *(const uint32_t*)(ap);
                a[mt][1] = *(const uint32_t*)(ap + 8 * AST);
                a[mt][2] = *(const uint32_t*)(ap + 8);
                a[mt][3] = *(const uint32_t*)(ap + 8 * AST + 8);
            }
#pragma unroll
            for (int nt = 0; nt < 4; nt++) {
                const __half* bp = bs + (wn * 32 + nt * 8 + gid) * AST + kk + tig * 2;
                uint32_t b0 = *(const uint32_t*)(bp);
                uint32_t b1 = *(const uint32_t*)(bp + 8);
#pragma unroll
                for (int mt = 0; mt < 2; mt++)
                    mma_f16(acc[mt][nt], a[mt], b0, b1);
            }
        }
        __syncthreads();
    }
#undef LOAD_STAGE

    // epilogue: c0,c1 -> (row g, cols tig*2,+1); c2,c3 -> (row g+8)
#pragma unroll
    for (int mt = 0; mt < 2; mt++) {
#pragma unroll
        for (int nt = 0; nt < 4; nt++) {
            int r  = wm * 32 + mt * 16 + gid;
            int cn = wn * 32 + nt * 8 + tig * 2;
            if (HALF_OUT) {
                __half* Ch = (__half*)C;
                *(__half2*)(Ch + (size_t)r * ldc + cn) =
                    __floats2half2_rn(acc[mt][nt][0], acc[mt][nt][1]);
                *(__half2*)(Ch + (size_t)(r + 8) * ldc + cn) =
                    __floats2half2_rn(acc[mt][nt][2], acc[mt][nt][3]);
            } else {
                float* Cf = (float*)C;
                *(float2*)(Cf + (size_t)r * ldc + cn) =
                    make_float2(acc[mt][nt][0], acc[mt][nt][1]);
                *(float2*)(Cf + (size_t)(r + 8) * ldc + cn) =
                    make_float2(acc[mt][nt][2], acc[mt][nt][3]);
            }
        }
    }
}

// ---------------- QKV grouped GEMM: grid (12, 32, 24) ----------------
__global__ void __launch_bounds__(256) gemm_qkv_kernel() {
    const int z   = blockIdx.z;
    const int mat = z >> 3;
    const int blk = z & 7;
    const __half* W = (mat == 0) ? g_wqt : (mat == 1) ? g_wkt : g_wvt;
    __half*       O = (mat == 0) ? g_q   : (mat == 1) ? g_k   : g_v;

    const __half* A = g_xh + (size_t)blockIdx.y * 128 * DIMX + blk * BLKD;
    const __half* B = W + (size_t)blk * BLKD * INNER + (size_t)blockIdx.x * 64 * BLKD;
    __half*       C = O + (size_t)blockIdx.y * 128 * QKVROW + blk * INNER + blockIdx.x * 64;
    gemm_body<true>(A, DIMX, B, BLKD, C, QKVROW, BLKD);
}

// ---------------- output projection: grid (2, 32, 8) ----------------
__global__ void __launch_bounds__(256) gemm_f_kernel(float* __restrict__ out) {
    const int blk = blockIdx.z;
    const __half* A = g_att + (size_t)blockIdx.y * 128 * QKVROW + blk * INNER;
    const __half* B = g_wft + (size_t)blk * BLKD * INNER + (size_t)blockIdx.x * 64 * INNER;
    float*        C = out + (size_t)blockIdx.y * 128 * DIMX + blk * BLKD + blockIdx.x * 64;
    gemm_body<false>(A, QKVROW, B, INNER, C, DIMX, INNER);
}

// ---------------- attention: 1 CTA per token, 1 warp per head ----------------
__global__ void __launch_bounds__(384) attn_kernel(float* __restrict__ smean) {
    const int t    = blockIdx.x;
    const int h    = threadIdx.x >> 5;
    const int lane = threadIdx.x & 31;

    __shared__ float sm[NHEAD][64];

    const size_t base = (size_t)t * QKVROW + h * HDIM;
    float2 q[8], k[8], v[8];
#pragma unroll
    for (int j = 0; j < 8; j++) {
        q[j] = __half22float2(((const __half2*)(g_q + base + j * INNER))[lane]);
        k[j] = __half22float2(((const __half2*)(g_k + base + j * INNER))[lane]);
        v[j] = __half22float2(((const __half2*)(g_v + base + j * INNER))[lane]);
    }

    float own0 = 0.f, own1 = 0.f;
#pragma unroll
    for (int i = 0; i < 8; i++) {
#pragma unroll
        for (int j = 0; j < 8; j++) {
            float p = q[i].x * k[j].x + q[i].y * k[j].y;
#pragma unroll
            for (int m = 16; m > 0; m >>= 1)
                p += __shfl_xor_sync(0xFFFFFFFFu, p, m);
            const int f = i * 8 + j;
            if (f < 32) { if (lane == f)        own0 = p; }
            else        { if (lane == (f & 31)) own1 = p; }
        }
    }
    own0 *= SCALE;
    own1 *= SCALE;

    float m0 = own0, m1 = own1;
#pragma unroll
    for (int m = 4; m >= 1; m >>= 1) {
        m0 = fmaxf(m0, __shfl_xor_sync(0xFFFFFFFFu, m0, m));
        m1 = fmaxf(m1, __shfl_xor_sync(0xFFFFFFFFu, m1, m));
    }
    float e0 = expf(own0 - m0), e1 = expf(own1 - m1);
    float s0 = e0, s1 = e1;
#pragma unroll
    for (int m = 4; m >= 1; m >>= 1) {
        s0 += __shfl_xor_sync(0xFFFFFFFFu, s0, m);
        s1 += __shfl_xor_sync(0xFFFFFFFFu, s1, m);
    }
    const float a0 = e0 / s0;
    const float a1 = e1 / s1;

    sm[h][lane]      = a0;
    sm[h][lane + 32] = a1;

    float2 acc[8];
#pragma unroll
    for (int i = 0; i < 8; i++) acc[i] = make_float2(0.f, 0.f);
#pragma unroll
    for (int i = 0; i < 8; i++) {
#pragma unroll
        for (int j = 0; j < 8; j++) {
            const int f = i * 8 + j;
            float aij = __shfl_sync(0xFFFFFFFFu, (f < 32) ? a0 : a1, f & 31);
            acc[i].x = fmaf(aij, v[j].x, acc[i].x);
            acc[i].y = fmaf(aij, v[j].y, acc[i].y);
        }
    }
#pragma unroll
    for (int i = 0; i < 8; i++) {
        *(__half2*)(g_att + (size_t)t * QKVROW + i * INNER + h * HDIM + 2 * lane) =
            __floats2half2_rn(acc[i].x, acc[i].y);
    }

    __syncthreads();
    if (smean != nullptr && threadIdx.x < 64) {
        float s = 0.f;
#pragma unroll
        for (int hh = 0; hh < NHEAD; hh++) s += sm[hh][threadIdx.x];
        smean[(size_t)t * 64 + threadIdx.x] = s * (1.0f / 12.0f);
    }
}

// ---------------- launch ----------------
extern "C" void kernel_launch(void* const* d_in, const int* in_sizes, int n_in,
                              void* d_out, int out_size) {
    const float* x  = (const float*)d_in[0];
    const float* Wq = (const float*)d_in[1];
    const float* Wk = (const float*)d_in[2];
    const float* Wv = (const float*)d_in[3];
    const float* Wf = (const float*)d_in[4];
    float* out = (float*)d_out;

    conv_x_kernel<<<SEQB * DIMX / 4 / 256, 256>>>(x);
    transpose_qkv_kernel<<<dim3(INNER / 32, BLKD / 32, 24), 256>>>(Wq, Wk, Wv);
    transpose_f_kernel<<<dim3(BLKD / 32, INNER / 32, NBLK), 256>>>(Wf);

    gemm_qkv_kernel<<<dim3(12, 32, 24), 256>>>();

    float* smean = (out_size >= SEQB * DIMX + SEQB * 64) ? (out + (size_t)SEQB * DIMX)
                                                         : nullptr;
    attn_kernel<<<SEQB, 384>>>(smean);

    gemm_f_kernel<<<dim3(2, 32, 8), 256>>>(out);
}

// round 4
// speedup vs baseline: 1.8250x; 1.1541x over previous
#include <cuda_runtime.h>
#include <cuda_fp16.h>
#include <cstdint>

// Problem constants
#define SEQB   4096
#define DIMX   1024
#define NBLK   8
#define BLKD   128
#define NHEAD  12
#define HDIM   64
#define INNER  768
#define QKVROW (NBLK*INNER)        // 6144
#define WELEM  (NBLK*BLKD*INNER)   // 786432
#define SCALE  0.125f

// smem tile: 128 rows x 32 halves (64B) per stage, XOR-swizzled at 16B granularity
#define TILE_BYTES 8192
#define SWZ(row, ch) (((row) * 64) + ((((ch) ^ (((row) >> 1) & 3)) << 4)))

// ---------------- scratch (device globals; allocation is forbidden) ----------------
__device__ __align__(16) __half g_xh [SEQB*DIMX];
__device__ __align__(16) __half g_wqt[WELEM];         // [blk][n=INNER][k=BLKD]
__device__ __align__(16) __half g_wkt[WELEM];
__device__ __align__(16) __half g_wvt[WELEM];
__device__ __align__(16) __half g_wft[WELEM];         // [blk][n=BLKD][k=INNER]
__device__ __align__(16) __half g_q  [SEQB*QKVROW];
__device__ __align__(16) __half g_k  [SEQB*QKVROW];
__device__ __align__(16) __half g_v  [SEQB*QKVROW];
__device__ __align__(16) __half g_att[SEQB*QKVROW];

// ---------------- helpers ----------------
__device__ __forceinline__ void mma_f16(float c[4], const uint32_t a[4],
                                        uint32_t b0, uint32_t b1) {
    asm volatile(
        "mma.sync.aligned.m16n8k16.row.col.f32.f16.f16.f32 "
        "{%0,%1,%2,%3}, {%4,%5,%6,%7}, {%8,%9}, {%0,%1,%2,%3};\n"
        : "+f"(c[0]), "+f"(c[1]), "+f"(c[2]), "+f"(c[3])
        : "r"(a[0]), "r"(a[1]), "r"(a[2]), "r"(a[3]), "r"(b0), "r"(b1));
}

__device__ __forceinline__ void ldsm4(uint32_t r[4], uint32_t addr) {
    asm volatile("ldmatrix.sync.aligned.m8n8.x4.shared.b16 {%0,%1,%2,%3}, [%4];"
                 : "=r"(r[0]), "=r"(r[1]), "=r"(r[2]), "=r"(r[3]) : "r"(addr));
}

__device__ __forceinline__ void cp_async16_s(uint32_t smem_dst, const __half* gmem_src) {
    asm volatile("cp.async.ca.shared.global [%0], [%1], 16;\n" :: "r"(smem_dst), "l"(gmem_src));
}
__device__ __forceinline__ void cp_commit() { asm volatile("cp.async.commit_group;\n"); }
__device__ __forceinline__ void cp_wait1()  { asm volatile("cp.async.wait_group 1;\n"); }
__device__ __forceinline__ void cp_wait0()  { asm volatile("cp.async.wait_group 0;\n"); }

// ---------------- prep: x -> half ----------------
__global__ void conv_x_kernel(const float* __restrict__ x) {
    int i = (blockIdx.x * blockDim.x + threadIdx.x) * 4;
    float4 v = *(const float4*)(x + i);
    __half2* o = (__half2*)(g_xh + i);
    o[0] = __floats2half2_rn(v.x, v.y);
    o[1] = __floats2half2_rn(v.z, v.w);
}

// ---------------- prep: transpose weights to [blk][n][k] half ----------------
__global__ void transpose_qkv_kernel(const float* __restrict__ wq,
                                     const float* __restrict__ wk,
                                     const float* __restrict__ wv) {
    __shared__ float tile[32][33];
    const int mat = blockIdx.z >> 3;
    const int blk = blockIdx.z & 7;
    const float* W = (mat == 0) ? wq : (mat == 1) ? wk : wv;
    __half* O      = (mat == 0) ? g_wqt : (mat == 1) ? g_wkt : g_wvt;
    const float* Wb = W + (size_t)blk * BLKD * INNER;   // [k=BLKD][n=INNER]
    __half* Ob      = O + (size_t)blk * BLKD * INNER;   // [n=INNER][k=BLKD]
    int n0 = blockIdx.x * 32, k0 = blockIdx.y * 32;
    int tx = threadIdx.x & 31, ty0 = threadIdx.x >> 5;
#pragma unroll
    for (int p = 0; p < 4; p++) {
        int ty = ty0 + p * 8;
        tile[ty][tx] = Wb[(size_t)(k0 + ty) * INNER + n0 + tx];
    }
    __syncthreads();
#pragma unroll
    for (int p = 0; p < 4; p++) {
        int ty = ty0 + p * 8;
        Ob[(size_t)(n0 + ty) * BLKD + k0 + tx] = __float2half_rn(tile[tx][ty]);
    }
}

__global__ void transpose_f_kernel(const float* __restrict__ wf) {
    __shared__ float tile[32][33];
    const int blk = blockIdx.z;
    const float* Wb = wf + (size_t)blk * INNER * BLKD;    // [k=INNER][n=BLKD]
    __half* Ob      = g_wft + (size_t)blk * INNER * BLKD; // [n=BLKD][k=INNER]
    int n0 = blockIdx.x * 32, k0 = blockIdx.y * 32;
    int tx = threadIdx.x & 31, ty0 = threadIdx.x >> 5;
#pragma unroll
    for (int p = 0; p < 4; p++) {
        int ty = ty0 + p * 8;
        tile[ty][tx] = Wb[(size_t)(k0 + ty) * BLKD + n0 + tx];
    }
    __syncthreads();
#pragma unroll
    for (int p = 0; p < 4; p++) {
        int ty = ty0 + p * 8;
        Ob[(size_t)(n0 + ty) * INNER + k0 + tx] = __float2half_rn(tile[tx][ty]);
    }
}

// ---------------- GEMM body: CTA 128(M) x 128(N), K-step 32, double-buffered -------
// 256 threads, 8 warps as 2(M) x 4(N); warp tile 64x32 via 4mt x 4nt m16n8k16.
// A row-major [m][k] half, B transposed [n][k] half. ldmatrix + XOR swizzle.
template <bool HALF_OUT>
__device__ __forceinline__ void gemm_body(const __half* __restrict__ A, int lda,
                                          const __half* __restrict__ B, int ldb,
                                          void* __restrict__ C, int ldc, int K) {
    __shared__ __align__(16) char As[2][TILE_BYTES];
    __shared__ __align__(16) char Bs[2][TILE_BYTES];

    const int tid  = threadIdx.x;
    const int lane = tid & 31;
    const int warp = tid >> 5;
    const int wm = warp & 1;        // 0..1: 64-row M slab
    const int wn = warp >> 1;       // 0..3: 32-col N slab
    const int gid = lane >> 2, tig = lane & 3;

    float acc[4][4][4];
#pragma unroll
    for (int mt = 0; mt < 4; mt++)
#pragma unroll
        for (int nt = 0; nt < 4; nt++)
#pragma unroll
            for (int e = 0; e < 4; e++) acc[mt][nt][e] = 0.f;

    const uint32_t as_base = (uint32_t)__cvta_generic_to_shared(As);
    const uint32_t bs_base = (uint32_t)__cvta_generic_to_shared(Bs);

    // loader: 512 16B chunks per tile; thread covers (row, row+64) at chunk (tid&3)
    const int l_row0 = tid >> 2;
    const int l_row1 = l_row0 + 64;
    const int l_c    = tid & 3;
    const uint32_t a_d0 = as_base + SWZ(l_row0, l_c);
    const uint32_t a_d1 = as_base + SWZ(l_row1, l_c);
    const uint32_t b_d0 = bs_base + SWZ(l_row0, l_c);
    const uint32_t b_d1 = bs_base + SWZ(l_row1, l_c);

#define LOAD_STAGE(st, kt)                                                        \
    do {                                                                          \
        const uint32_t so = (st) * TILE_BYTES;                                    \
        cp_async16_s(a_d0 + so, A + (size_t)l_row0 * lda + (kt) + l_c * 8);       \
        cp_async16_s(a_d1 + so, A + (size_t)l_row1 * lda + (kt) + l_c * 8);       \
        cp_async16_s(b_d0 + so, B + (size_t)l_row0 * ldb + (kt) + l_c * 8);       \
        cp_async16_s(b_d1 + so, B + (size_t)l_row1 * ldb + (kt) + l_c * 8);       \
        cp_commit();                                                              \
    } while (0)

    // per-lane fragment source rows (swizzle applied inline per k-step)
    int a_row[4], b_row[2];
#pragma unroll
    for (int mt = 0; mt < 4; mt++)
        a_row[mt] = wm * 64 + mt * 16 + (lane & 7) + ((lane >> 3) & 1) * 8;
#pragma unroll
    for (int np = 0; np < 2; np++)
        b_row[np] = wn * 32 + np * 16 + (lane & 7) + ((lane >> 4) & 1) * 8;
    const int ac = lane >> 4;          // A chunk offset (0/1)
    const int bc = (lane >> 3) & 1;    // B chunk offset (0/1)

    const int nK = K / 32;
    LOAD_STAGE(0, 0);

    for (int t = 0; t < nK; t++) {
        if (t + 1 < nK) { LOAD_STAGE((t + 1) & 1, (t + 1) * 32); cp_wait1(); }
        else            { cp_wait0(); }
        __syncthreads();

        const uint32_t ab = as_base + (t & 1) * TILE_BYTES;
        const uint32_t bb = bs_base + (t & 1) * TILE_BYTES;
#pragma unroll
        for (int ks = 0; ks < 2; ks++) {
            const int kb = ks * 2;
            uint32_t a[4][4];
#pragma unroll
            for (int mt = 0; mt < 4; mt++)
                ldsm4(a[mt], ab + SWZ(a_row[mt], kb + ac));
            uint32_t bf[2][4];
#pragma unroll
            for (int np = 0; np < 2; np++)
                ldsm4(bf[np], bb + SWZ(b_row[np], kb + bc));
#pragma unroll
            for (int mt = 0; mt < 4; mt++) {
#pragma unroll
                for (int np = 0; np < 2; np++) {
                    mma_f16(acc[mt][np * 2 + 0], a[mt], bf[np][0], bf[np][1]);
                    mma_f16(acc[mt][np * 2 + 1], a[mt], bf[np][2], bf[np][3]);
                }
            }
        }
        __syncthreads();
    }
#undef LOAD_STAGE

    // epilogue
#pragma unroll
    for (int mt = 0; mt < 4; mt++) {
#pragma unroll
        for (int nt = 0; nt < 4; nt++) {
            int r  = wm * 64 + mt * 16 + gid;
            int cn = wn * 32 + nt * 8 + tig * 2;
            if (HALF_OUT) {
                __half* Ch = (__half*)C;
                *(__half2*)(Ch + (size_t)r * ldc + cn) =
                    __floats2half2_rn(acc[mt][nt][0], acc[mt][nt][1]);
                *(__half2*)(Ch + (size_t)(r + 8) * ldc + cn) =
                    __floats2half2_rn(acc[mt][nt][2], acc[mt][nt][3]);
            } else {
                float* Cf = (float*)C;
                *(float2*)(Cf + (size_t)r * ldc + cn) =
                    make_float2(acc[mt][nt][0], acc[mt][nt][1]);
                *(float2*)(Cf + (size_t)(r + 8) * ldc + cn) =
                    make_float2(acc[mt][nt][2], acc[mt][nt][3]);
            }
        }
    }
}

// ---------------- QKV grouped GEMM: grid (6, 32, 24) ----------------
__global__ void __launch_bounds__(256) gemm_qkv_kernel() {
    const int z   = blockIdx.z;
    const int mat = z >> 3;
    const int blk = z & 7;
    const __half* W = (mat == 0) ? g_wqt : (mat == 1) ? g_wkt : g_wvt;
    __half*       O = (mat == 0) ? g_q   : (mat == 1) ? g_k   : g_v;

    const __half* A = g_xh + (size_t)blockIdx.y * 128 * DIMX + blk * BLKD;
    const __half* B = W + (size_t)blk * BLKD * INNER + (size_t)blockIdx.x * 128 * BLKD;
    __half*       C = O + (size_t)blockIdx.y * 128 * QKVROW + blk * INNER + blockIdx.x * 128;
    gemm_body<true>(A, DIMX, B, BLKD, C, QKVROW, BLKD);
}

// ---------------- output projection: grid (1, 32, 8) ----------------
__global__ void __launch_bounds__(256) gemm_f_kernel(float* __restrict__ out) {
    const int blk = blockIdx.z;
    const __half* A = g_att + (size_t)blockIdx.y * 128 * QKVROW + blk * INNER;
    const __half* B = g_wft + (size_t)blk * BLKD * INNER;
    float*        C = out + (size_t)blockIdx.y * 128 * DIMX + blk * BLKD;
    gemm_body<false>(A, QKVROW, B, INNER, C, DIMX, INNER);
}

// ---------------- attention: 1 CTA per token, 1 warp per head ----------------
__global__ void __launch_bounds__(384) attn_kernel(float* __restrict__ smean) {
    const int t    = blockIdx.x;
    const int h    = threadIdx.x >> 5;
    const int lane = threadIdx.x & 31;

    __shared__ float sm[NHEAD][64];

    const size_t base = (size_t)t * QKVROW + h * HDIM;
    float2 q[8], k[8], v[8];
#pragma unroll
    for (int j = 0; j < 8; j++) {
        q[j] = __half22float2(((const __half2*)(g_q + base + j * INNER))[lane]);
        k[j] = __half22float2(((const __half2*)(g_k + base + j * INNER))[lane]);
        v[j] = __half22float2(((const __half2*)(g_v + base + j * INNER))[lane]);
    }

    float own0 = 0.f, own1 = 0.f;
#pragma unroll
    for (int i = 0; i < 8; i++) {
#pragma unroll
        for (int j = 0; j < 8; j++) {
            float p = q[i].x * k[j].x + q[i].y * k[j].y;
#pragma unroll
            for (int m = 16; m > 0; m >>= 1)
                p += __shfl_xor_sync(0xFFFFFFFFu, p, m);
            const int f = i * 8 + j;
            if (f < 32) { if (lane == f)        own0 = p; }
            else        { if (lane == (f & 31)) own1 = p; }
        }
    }
    own0 *= SCALE;
    own1 *= SCALE;

    float m0 = own0, m1 = own1;
#pragma unroll
    for (int m = 4; m >= 1; m >>= 1) {
        m0 = fmaxf(m0, __shfl_xor_sync(0xFFFFFFFFu, m0, m));
        m1 = fmaxf(m1, __shfl_xor_sync(0xFFFFFFFFu, m1, m));
    }
    float e0 = expf(own0 - m0), e1 = expf(own1 - m1);
    float s0 = e0, s1 = e1;
#pragma unroll
    for (int m = 4; m >= 1; m >>= 1) {
        s0 += __shfl_xor_sync(0xFFFFFFFFu, s0, m);
        s1 += __shfl_xor_sync(0xFFFFFFFFu, s1, m);
    }
    const float a0 = e0 / s0;
    const float a1 = e1 / s1;

    sm[h][lane]      = a0;
    sm[h][lane + 32] = a1;

    float2 acc[8];
#pragma unroll
    for (int i = 0; i < 8; i++) acc[i] = make_float2(0.f, 0.f);
#pragma unroll
    for (int i = 0; i < 8; i++) {
#pragma unroll
        for (int j = 0; j < 8; j++) {
            const int f = i * 8 + j;
            float aij = __shfl_sync(0xFFFFFFFFu, (f < 32) ? a0 : a1, f & 31);
            acc[i].x = fmaf(aij, v[j].x, acc[i].x);
            acc[i].y = fmaf(aij, v[j].y, acc[i].y);
        }
    }
#pragma unroll
    for (int i = 0; i < 8; i++) {
        *(__half2*)(g_att + (size_t)t * QKVROW + i * INNER + h * HDIM + 2 * lane) =
            __floats2half2_rn(acc[i].x, acc[i].y);
    }

    __syncthreads();
    if (smean != nullptr && threadIdx.x < 64) {
        float s = 0.f;
#pragma unroll
        for (int hh = 0; hh < NHEAD; hh++) s += sm[hh][threadIdx.x];
        smean[(size_t)t * 64 + threadIdx.x] = s * (1.0f / 12.0f);
    }
}

// ---------------- launch ----------------
extern "C" void kernel_launch(void* const* d_in, const int* in_sizes, int n_in,
                              void* d_out, int out_size) {
    const float* x  = (const float*)d_in[0];
    const float* Wq = (const float*)d_in[1];
    const float* Wk = (const float*)d_in[2];
    const float* Wv = (const float*)d_in[3];
    const float* Wf = (const float*)d_in[4];
    float* out = (float*)d_out;

    conv_x_kernel<<<SEQB * DIMX / 4 / 256, 256>>>(x);
    transpose_qkv_kernel<<<dim3(INNER / 32, BLKD / 32, 24), 256>>>(Wq, Wk, Wv);
    transpose_f_kernel<<<dim3(BLKD / 32, INNER / 32, NBLK), 256>>>(Wf);

    gemm_qkv_kernel<<<dim3(6, 32, 24), 256>>>();

    float* smean = (out_size >= SEQB * DIMX + SEQB * 64) ? (out + (size_t)SEQB * DIMX)
                                                         : nullptr;
    attn_kernel<<<SEQB, 384>>>(smean);

    gemm_f_kernel<<<dim3(1, 32, 8), 256>>>(out);
}

// round 6
// speedup vs baseline: 1.8421x; 1.0094x over previous
#include <cuda_runtime.h>
#include <cuda_fp16.h>
#include <cstdint>

// Problem constants
#define SEQB   4096
#define DIMX   1024
#define NBLK   8
#define BLKD   128
#define NHEAD  12
#define HDIM   64
#define INNER  768
#define QKVROW (NBLK*INNER)        // 6144
#define WELEM  (NBLK*BLKD*INNER)   // 786432
#define SCALE  0.125f

// 128x32-half subtile (8KB), 64B rows, XOR-swizzled at 16B granularity
#define SUB_BYTES 8192
#define SWZ(row, ch) (((row) * 64) + ((((ch) ^ (((row) >> 1) & 3)) << 4)))

#define QKV_DSM (8*SUB_BYTES + 1024)    // 4 A subtiles + 4 B subtiles
#define F_DSM   (12*SUB_BYTES + 1024)   // 3 stages x (2A + 2B) subtiles

// ---------------- scratch (device globals; allocation is forbidden) ----------------
__device__ __align__(16) __half g_xh [SEQB*DIMX];
__device__ __align__(16) __half g_wqt[WELEM];         // [blk][n=INNER][k=BLKD]
__device__ __align__(16) __half g_wkt[WELEM];
__device__ __align__(16) __half g_wvt[WELEM];
__device__ __align__(16) __half g_wft[WELEM];         // [blk][n=BLKD][k=INNER]
__device__ __align__(16) __half g_q  [SEQB*QKVROW];
__device__ __align__(16) __half g_k  [SEQB*QKVROW];
__device__ __align__(16) __half g_v  [SEQB*QKVROW];
__device__ __align__(16) __half g_att[SEQB*QKVROW];

// ---------------- helpers ----------------
__device__ __forceinline__ void mma_f16(float c[4], const uint32_t a[4],
                                        uint32_t b0, uint32_t b1) {
    asm volatile(
        "mma.sync.aligned.m16n8k16.row.col.f32.f16.f16.f32 "
        "{%0,%1,%2,%3}, {%4,%5,%6,%7}, {%8,%9}, {%0,%1,%2,%3};\n"
        : "+f"(c[0]), "+f"(c[1]), "+f"(c[2]), "+f"(c[3])
        : "r"(a[0]), "r"(a[1]), "r"(a[2]), "r"(a[3]), "r"(b0), "r"(b1));
}

__device__ __forceinline__ void ldsm4(uint32_t r[4], uint32_t addr) {
    asm volatile("ldmatrix.sync.aligned.m8n8.x4.shared.b16 {%0,%1,%2,%3}, [%4];"
                 : "=r"(r[0]), "=r"(r[1]), "=r"(r[2]), "=r"(r[3]) : "r"(addr));
}

__device__ __forceinline__ void cpa16(uint32_t smem_dst, const __half* gmem_src) {
    asm volatile("cp.async.ca.shared.global [%0], [%1], 16;\n" :: "r"(smem_dst), "l"(gmem_src));
}
__device__ __forceinline__ void cp_commit() { asm volatile("cp.async.commit_group;\n"); }
template <int N>
__device__ __forceinline__ void cp_wait() { asm volatile("cp.async.wait_group %0;\n" :: "n"(N)); }

__device__ __forceinline__ uint32_t s2u(const void* p) {
    return (uint32_t)__cvta_generic_to_shared(p);
}

// ---------------- prep: x -> half ----------------
__global__ void conv_x_kernel(const float* __restrict__ x) {
    int i = (blockIdx.x * blockDim.x + threadIdx.x) * 4;
    float4 v = *(const float4*)(x + i);
    __half2* o = (__half2*)(g_xh + i);
    o[0] = __floats2half2_rn(v.x, v.y);
    o[1] = __floats2half2_rn(v.z, v.w);
}

// ---------------- prep: transpose weights to [blk][n][k] half ----------------
__global__ void transpose_qkv_kernel(const float* __restrict__ wq,
                                     const float* __restrict__ wk,
                                     const float* __restrict__ wv) {
    __shared__ float tile[32][33];
    const int mat = blockIdx.z >> 3;
    const int blk = blockIdx.z & 7;
    const float* W = (mat == 0) ? wq : (mat == 1) ? wk : wv;
    __half* O      = (mat == 0) ? g_wqt : (mat == 1) ? g_wkt : g_wvt;
    const float* Wb = W + (size_t)blk * BLKD * INNER;   // [k=BLKD][n=INNER]
    __half* Ob      = O + (size_t)blk * BLKD * INNER;   // [n=INNER][k=BLKD]
    int n0 = blockIdx.x * 32, k0 = blockIdx.y * 32;
    int tx = threadIdx.x & 31, ty0 = threadIdx.x >> 5;
#pragma unroll
    for (int p = 0; p < 4; p++) {
        int ty = ty0 + p * 8;
        tile[ty][tx] = Wb[(size_t)(k0 + ty) * INNER + n0 + tx];
    }
    __syncthreads();
#pragma unroll
    for (int p = 0; p < 4; p++) {
        int ty = ty0 + p * 8;
        Ob[(size_t)(n0 + ty) * BLKD + k0 + tx] = __float2half_rn(tile[tx][ty]);
    }
}

__global__ void transpose_f_kernel(const float* __restrict__ wf) {
    __shared__ float tile[32][33];
    const int blk = blockIdx.z;
    const float* Wb = wf + (size_t)blk * INNER * BLKD;    // [k=INNER][n=BLKD]
    __half* Ob      = g_wft + (size_t)blk * INNER * BLKD; // [n=BLKD][k=INNER]
    int n0 = blockIdx.x * 32, k0 = blockIdx.y * 32;
    int tx = threadIdx.x & 31, ty0 = threadIdx.x >> 5;
#pragma unroll
    for (int p = 0; p < 4; p++) {
        int ty = ty0 + p * 8;
        tile[ty][tx] = Wb[(size_t)(k0 + ty) * BLKD + n0 + tx];
    }
    __syncthreads();
#pragma unroll
    for (int p = 0; p < 4; p++) {
        int ty = ty0 + p * 8;
        Ob[(size_t)(n0 + ty) * INNER + k0 + tx] = __float2half_rn(tile[tx][ty]);
    }
}

// ---------------- shared mma core: one 128x128x32 subtile step ----------------
// 8 warps as 2(M) x 4(N); warp tile 64x32 via 4mt x 4nt m16n8k16. ldsm + swizzle.
struct FragCtx {
    int a_row[4];
    int b_row[2];
    int ac, bc;
};

__device__ __forceinline__ void frag_init(FragCtx& f, int lane, int wm, int wn) {
#pragma unroll
    for (int mt = 0; mt < 4; mt++)
        f.a_row[mt] = wm * 64 + mt * 16 + (lane & 7) + ((lane >> 3) & 1) * 8;
#pragma unroll
    for (int np = 0; np < 2; np++)
        f.b_row[np] = wn * 32 + np * 16 + (lane & 7) + ((lane >> 4) & 1) * 8;
    f.ac = lane >> 4;
    f.bc = (lane >> 3) & 1;
}

__device__ __forceinline__ void compute_k32(uint32_t ab, uint32_t bb, const FragCtx& f,
                                            float acc[4][4][4]) {
#pragma unroll
    for (int ks = 0; ks < 2; ks++) {
        const int kb = ks * 2;
        uint32_t a[4][4];
#pragma unroll
        for (int mt = 0; mt < 4; mt++)
            ldsm4(a[mt], ab + SWZ(f.a_row[mt], kb + f.ac));
        uint32_t bf[2][4];
#pragma unroll
        for (int np = 0; np < 2; np++)
            ldsm4(bf[np], bb + SWZ(f.b_row[np], kb + f.bc));
#pragma unroll
        for (int mt = 0; mt < 4; mt++) {
#pragma unroll
            for (int np = 0; np < 2; np++) {
                mma_f16(acc[mt][np * 2 + 0], a[mt], bf[np][0], bf[np][1]);
                mma_f16(acc[mt][np * 2 + 1], a[mt], bf[np][2], bf[np][3]);
            }
        }
    }
}

// load one 128x32 subtile (row-major src, row stride ld halves); 256 threads, 2 cp each
__device__ __forceinline__ void load_sub(uint32_t dst, const __half* __restrict__ src, int ld) {
    const int tid = threadIdx.x;
    const int r0 = tid >> 2, c = tid & 3;
    cpa16(dst + SWZ(r0, c),      src + (size_t)r0 * ld + c * 8);
    cpa16(dst + SWZ(r0 + 64, c), src + (size_t)(r0 + 64) * ld + c * 8);
}

// ---------------- QKV: single-shot K=128, grid (6, 32, 24), 256 thr ----------------
__global__ void __launch_bounds__(256, 2) gemm_qkv_kernel() {
    extern __shared__ __align__(16) char dsm[];
    char* base = (char*)(((uintptr_t)dsm + 1023) & ~(uintptr_t)1023);
    const uint32_t sb = s2u(base);          // A subs: sb + t*8KB; B subs: sb+32KB + t*8KB

    const int tid  = threadIdx.x;
    const int lane = tid & 31;
    const int warp = tid >> 5;
    const int wm = warp & 1, wn = warp >> 1;
    const int gid = lane >> 2, tig = lane & 3;

    const int z = blockIdx.z, mat = z >> 3, blk = z & 7;
    const __half* W = (mat == 0) ? g_wqt : (mat == 1) ? g_wkt : g_wvt;
    __half*       O = (mat == 0) ? g_q   : (mat == 1) ? g_k   : g_v;
    const __half* A = g_xh + (size_t)blockIdx.y * 128 * DIMX + blk * BLKD;
    const __half* B = W + (size_t)blk * BLKD * INNER + (size_t)blockIdx.x * 128 * BLKD;
    __half*       C = O + (size_t)blockIdx.y * 128 * QKVROW + blk * INNER + blockIdx.x * 128;

    // one burst: whole 64KB (A: 4 subtiles, B: 4 subtiles)
#pragma unroll
    for (int t = 0; t < 4; t++) {
        load_sub(sb + t * SUB_BYTES,                 A + t * 32, DIMX);
        load_sub(sb + 4 * SUB_BYTES + t * SUB_BYTES, B + t * 32, BLKD);
    }
    cp_commit();

    FragCtx f;
    frag_init(f, lane, wm, wn);
    float acc[4][4][4];
#pragma unroll
    for (int mt = 0; mt < 4; mt++)
#pragma unroll
        for (int nt = 0; nt < 4; nt++)
#pragma unroll
            for (int e = 0; e < 4; e++) acc[mt][nt][e] = 0.f;

    cp_wait<0>();
    __syncthreads();

#pragma unroll
    for (int t = 0; t < 4; t++)
        compute_k32(sb + t * SUB_BYTES, sb + (4 + t) * SUB_BYTES, f, acc);

    // epilogue (half out)
#pragma unroll
    for (int mt = 0; mt < 4; mt++) {
#pragma unroll
        for (int nt = 0; nt < 4; nt++) {
            int r  = wm * 64 + mt * 16 + gid;
            int cn = wn * 32 + nt * 8 + tig * 2;
            *(__half2*)(C + (size_t)r * QKVROW + cn) =
                __floats2half2_rn(acc[mt][nt][0], acc[mt][nt][1]);
            *(__half2*)(C + (size_t)(r + 8) * QKVROW + cn) =
                __floats2half2_rn(acc[mt][nt][2], acc[mt][nt][3]);
        }
    }
}

// ---------------- output projection: K=768 as 12 k64 chunks, 3-stage ring ----------
// grid (32, 8), 256 threads, 96KB smem -> 2 CTAs/SM -> single wave.
__global__ void __launch_bounds__(256, 2) gemm_f_kernel(float* __restrict__ out) {
    extern __shared__ __align__(16) char dsm[];
    char* base = (char*)(((uintptr_t)dsm + 1023) & ~(uintptr_t)1023);
    const uint32_t sb = s2u(base);
    // stage s (0..2): A subs at sb + s*32KB + {0,8KB}; B subs at + 16KB + {0,8KB}

    const int tid  = threadIdx.x;
    const int lane = tid & 31;
    const int warp = tid >> 5;
    const int wm = warp & 1, wn = warp >> 1;
    const int gid = lane >> 2, tig = lane & 3;

    const int blk = blockIdx.y;
    const __half* A = g_att + (size_t)blockIdx.x * 128 * QKVROW + blk * INNER;
    const __half* B = g_wft + (size_t)blk * BLKD * INNER;
    float*        C = out + (size_t)blockIdx.x * 128 * DIMX + blk * BLKD;

#define LOAD_CHUNK(c, s)                                                           \
    do {                                                                           \
        const uint32_t st = sb + (uint32_t)(s) * (4 * SUB_BYTES);                  \
        load_sub(st,                 A + (c) * 64,      QKVROW);                   \
        load_sub(st + SUB_BYTES,     A + (c) * 64 + 32, QKVROW);                   \
        load_sub(st + 2 * SUB_BYTES, B + (c) * 64,      INNER);                    \
        load_sub(st + 3 * SUB_BYTES, B + (c) * 64 + 32, INNER);                    \
        cp_commit();                                                               \
    } while (0)

    FragCtx f;
    frag_init(f, lane, wm, wn);
    float acc[4][4][4];
#pragma unroll
    for (int mt = 0; mt < 4; mt++)
#pragma unroll
        for (int nt = 0; nt < 4; nt++)
#pragma unroll
            for (int e = 0; e < 4; e++) acc[mt][nt][e] = 0.f;

    LOAD_CHUNK(0, 0);
    LOAD_CHUNK(1, 1);

    for (int t = 0; t < 12; t++) {
        if (t + 2 < 12) LOAD_CHUNK(t + 2, (t + 2) % 3);
        const int ahead = (12 - 1 - t < 2) ? (12 - 1 - t) : 2;
        if      (ahead == 2) cp_wait<2>();
        else if (ahead == 1) cp_wait<1>();
        else                 cp_wait<0>();
        __syncthreads();

        const uint32_t st = sb + (uint32_t)(t % 3) * (4 * SUB_BYTES);
        compute_k32(st,             st + 2 * SUB_BYTES, f, acc);
        compute_k32(st + SUB_BYTES, st + 3 * SUB_BYTES, f, acc);
        __syncthreads();
    }
#undef LOAD_CHUNK

    // epilogue (float out)
#pragma unroll
    for (int mt = 0; mt < 4; mt++) {
#pragma unroll
        for (int nt = 0; nt < 4; nt++) {
            int r  = wm * 64 + mt * 16 + gid;
            int cn = wn * 32 + nt * 8 + tig * 2;
            *(float2*)(C + (size_t)r * DIMX + cn) =
                make_float2(acc[mt][nt][0], acc[mt][nt][1]);
            *(float2*)(C + (size_t)(r + 8) * DIMX + cn) =
                make_float2(acc[mt][nt][2], acc[mt][nt][3]);
        }
    }
}

// ---------------- attention: 1 CTA per token, 1 warp per head ----------------
__global__ void __launch_bounds__(384) attn_kernel(float* __restrict__ smean) {
    const int t    = blockIdx.x;
    const int h    = threadIdx.x >> 5;
    const int lane = threadIdx.x & 31;

    __shared__ float sm[NHEAD][64];

    const size_t base = (size_t)t * QKVROW + h * HDIM;
    float2 q[8], k[8], v[8];
#pragma unroll
    for (int j = 0; j < 8; j++) {
        q[j] = __half22float2(((const __half2*)(g_q + base + j * INNER))[lane]);
        k[j] = __half22float2(((const __half2*)(g_k + base + j * INNER))[lane]);
        v[j] = __half22float2(((const __half2*)(g_v + base + j * INNER))[lane]);
    }

    float own0 = 0.f, own1 = 0.f;
#pragma unroll
    for (int i = 0; i < 8; i++) {
#pragma unroll
        for (int j = 0; j < 8; j++) {
            float p = q[i].x * k[j].x + q[i].y * k[j].y;
#pragma unroll
            for (int m = 16; m > 0; m >>= 1)
                p += __shfl_xor_sync(0xFFFFFFFFu, p, m);
            const int f = i * 8 + j;
            if (f < 32) { if (lane == f)        own0 = p; }
            else        { if (lane == (f & 31)) own1 = p; }
        }
    }
    own0 *= SCALE;
    own1 *= SCALE;

    float m0 = own0, m1 = own1;
#pragma unroll
    for (int m = 4; m >= 1; m >>= 1) {
        m0 = fmaxf(m0, __shfl_xor_sync(0xFFFFFFFFu, m0, m));
        m1 = fmaxf(m1, __shfl_xor_sync(0xFFFFFFFFu, m1, m));
    }
    float e0 = expf(own0 - m0), e1 = expf(own1 - m1);
    float s0 = e0, s1 = e1;
#pragma unroll
    for (int m = 4; m >= 1; m >>= 1) {
        s0 += __shfl_xor_sync(0xFFFFFFFFu, s0, m);
        s1 += __shfl_xor_sync(0xFFFFFFFFu, s1, m);
    }
    const float a0 = e0 / s0;
    const float a1 = e1 / s1;

    sm[h][lane]      = a0;
    sm[h][lane + 32] = a1;

    float2 acc[8];
#pragma unroll
    for (int i = 0; i < 8; i++) acc[i] = make_float2(0.f, 0.f);
#pragma unroll
    for (int i = 0; i < 8; i++) {
#pragma unroll
        for (int j = 0; j < 8; j++) {
            const int f = i * 8 + j;
            float aij = __shfl_sync(0xFFFFFFFFu, (f < 32) ? a0 : a1, f & 31);
            acc[i].x = fmaf(aij, v[j].x, acc[i].x);
            acc[i].y = fmaf(aij, v[j].y, acc[i].y);
        }
    }
#pragma unroll
    for (int i = 0; i < 8; i++) {
        *(__half2*)(g_att + (size_t)t * QKVROW + i * INNER + h * HDIM + 2 * lane) =
            __floats2half2_rn(acc[i].x, acc[i].y);
    }

    __syncthreads();
    if (smean != nullptr && threadIdx.x < 64) {
        float s = 0.f;
#pragma unroll
        for (int hh = 0; hh < NHEAD; hh++) s += sm[hh][threadIdx.x];
        smean[(size_t)t * 64 + threadIdx.x] = s * (1.0f / 12.0f);
    }
}

// ---------------- launch ----------------
extern "C" void kernel_launch(void* const* d_in, const int* in_sizes, int n_in,
                              void* d_out, int out_size) {
    const float* x  = (const float*)d_in[0];
    const float* Wq = (const float*)d_in[1];
    const float* Wk = (const float*)d_in[2];
    const float* Wv = (const float*)d_in[3];
    const float* Wf = (const float*)d_in[4];
    float* out = (float*)d_out;

    cudaFuncSetAttribute(gemm_qkv_kernel, cudaFuncAttributeMaxDynamicSharedMemorySize, QKV_DSM);
    cudaFuncSetAttribute(gemm_f_kernel,   cudaFuncAttributeMaxDynamicSharedMemorySize, F_DSM);

    conv_x_kernel<<<SEQB * DIMX / 4 / 256, 256>>>(x);
    transpose_qkv_kernel<<<dim3(INNER / 32, BLKD / 32, 24), 256>>>(Wq, Wk, Wv);
    transpose_f_kernel<<<dim3(BLKD / 32, INNER / 32, NBLK), 256>>>(Wf);

    gemm_qkv_kernel<<<dim3(6, 32, 24), 256, QKV_DSM>>>();

    float* smean = (out_size >= SEQB * DIMX + SEQB * 64) ? (out + (size_t)SEQB * DIMX)
                                                         : nullptr;
    attn_kernel<<<SEQB, 384>>>(smean);

    gemm_f_kernel<<<dim3(32, NBLK), 256, F_DSM>>>(out);
}

// round 8
// speedup vs baseline: 1.8917x; 1.0269x over previous
#include <cuda_runtime.h>
#include <cuda_fp16.h>
#include <cstdint>

// Problem constants
#define SEQB   4096
#define DIMX   1024
#define NBLK   8
#define BLKD   128
#define NHEAD  12
#define HDIM   64
#define INNER  768
#define QKVROW (NBLK*INNER)        // 6144
#define WELEM  (NBLK*BLKD*INNER)   // 786432
#define SCALE  0.125f

// 128x32-half subtile (8KB), 64B rows, XOR-swizzled at 16B granularity
#define SUB_BYTES 8192
#define SWZ(row, ch) (((row) * 64) + ((((ch) ^ (((row) >> 1) & 3)) << 4)))

#define QKV_DSM (8*SUB_BYTES + 1024)    // 4 A + 4 B subtiles (64KB)
#define F_DSM   (8*SUB_BYTES + 1024)    // 2 stages x (2A + 2B)

// ---------------- scratch (device globals; allocation is forbidden) ----------------
__device__ __align__(16) __half g_xh [SEQB*DIMX];
__device__ __align__(16) __half g_wqt[WELEM];         // [blk][n=INNER][k=BLKD]
__device__ __align__(16) __half g_wkt[WELEM];
__device__ __align__(16) __half g_wvt[WELEM];
__device__ __align__(16) __half g_wft[WELEM];         // [blk][n=BLKD][k=INNER]
__device__ __align__(16) __half g_q  [SEQB*QKVROW];
__device__ __align__(16) __half g_k  [SEQB*QKVROW];
__device__ __align__(16) __half g_v  [SEQB*QKVROW];
__device__ __align__(16) __half g_att[SEQB*QKVROW];

// ---------------- helpers ----------------
__device__ __forceinline__ void mma_f16(float c[4], const uint32_t a[4],
                                        uint32_t b0, uint32_t b1) {
    asm volatile(
        "mma.sync.aligned.m16n8k16.row.col.f32.f16.f16.f32 "
        "{%0,%1,%2,%3}, {%4,%5,%6,%7}, {%8,%9}, {%0,%1,%2,%3};\n"
        : "+f"(c[0]), "+f"(c[1]), "+f"(c[2]), "+f"(c[3])
        : "r"(a[0]), "r"(a[1]), "r"(a[2]), "r"(a[3]), "r"(b0), "r"(b1));
}

__device__ __forceinline__ void ldsm4(uint32_t r[4], uint32_t addr) {
    asm volatile("ldmatrix.sync.aligned.m8n8.x4.shared.b16 {%0,%1,%2,%3}, [%4];"
                 : "=r"(r[0]), "=r"(r[1]), "=r"(r[2]), "=r"(r[3]) : "r"(addr));
}

__device__ __forceinline__ void cpa16(uint32_t smem_dst, const __half* gmem_src) {
    asm volatile("cp.async.ca.shared.global [%0], [%1], 16;\n" :: "r"(smem_dst), "l"(gmem_src));
}
__device__ __forceinline__ void cp_commit() { asm volatile("cp.async.commit_group;\n"); }
template <int N>
__device__ __forceinline__ void cp_wait() { asm volatile("cp.async.wait_group %0;\n" :: "n"(N)); }

__device__ __forceinline__ uint32_t s2u(const void* p) {
    return (uint32_t)__cvta_generic_to_shared(p);
}

// ---------------- prep: x -> half ----------------
__global__ void conv_x_kernel(const float* __restrict__ x) {
    int i = (blockIdx.x * blockDim.x + threadIdx.x) * 4;
    float4 v = *(const float4*)(x + i);
    __half2* o = (__half2*)(g_xh + i);
    o[0] = __floats2half2_rn(v.x, v.y);
    o[1] = __floats2half2_rn(v.z, v.w);
}

// ---------------- prep: transpose weights to [blk][n][k] half ----------------
__global__ void transpose_qkv_kernel(const float* __restrict__ wq,
                                     const float* __restrict__ wk,
                                     const float* __restrict__ wv) {
    __shared__ float tile[32][33];
    const int mat = blockIdx.z >> 3;
    const int blk = blockIdx.z & 7;
    const float* W = (mat == 0) ? wq : (mat == 1) ? wk : wv;
    __half* O      = (mat == 0) ? g_wqt : (mat == 1) ? g_wkt : g_wvt;
    const float* Wb = W + (size_t)blk * BLKD * INNER;   // [k=BLKD][n=INNER]
    __half* Ob      = O + (size_t)blk * BLKD * INNER;   // [n=INNER][k=BLKD]
    int n0 = blockIdx.x * 32, k0 = blockIdx.y * 32;
    int tx = threadIdx.x & 31, ty0 = threadIdx.x >> 5;
#pragma unroll
    for (int p = 0; p < 4; p++) {
        int ty = ty0 + p * 8;
        tile[ty][tx] = Wb[(size_t)(k0 + ty) * INNER + n0 + tx];
    }
    __syncthreads();
#pragma unroll
    for (int p = 0; p < 4; p++) {
        int ty = ty0 + p * 8;
        Ob[(size_t)(n0 + ty) * BLKD + k0 + tx] = __float2half_rn(tile[tx][ty]);
    }
}

__global__ void transpose_f_kernel(const float* __restrict__ wf) {
    __shared__ float tile[32][33];
    const int blk = blockIdx.z;
    const float* Wb = wf + (size_t)blk * INNER * BLKD;    // [k=INNER][n=BLKD]
    __half* Ob      = g_wft + (size_t)blk * INNER * BLKD; // [n=BLKD][k=INNER]
    int n0 = blockIdx.x * 32, k0 = blockIdx.y * 32;
    int tx = threadIdx.x & 31, ty0 = threadIdx.x >> 5;
#pragma unroll
    for (int p = 0; p < 4; p++) {
        int ty = ty0 + p * 8;
        tile[ty][tx] = Wb[(size_t)(k0 + ty) * BLKD + n0 + tx];
    }
    __syncthreads();
#pragma unroll
    for (int p = 0; p < 4; p++) {
        int ty = ty0 + p * 8;
        Ob[(size_t)(n0 + ty) * INNER + k0 + tx] = __float2half_rn(tile[tx][ty]);
    }
}

// ---------------- mma core: warp tile 64(M) x 64(N), CTA 128x128, 4 warps ---------
// warps as 2(M) x 2(N); per k32: 8 A-ldsm4 + 8 B-ldsm4, 64 mma. acc[4][8][4].
struct FragCtx {
    int a_row[4];
    int b_row[4];
    int ac, bc;
};

__device__ __forceinline__ void frag_init(FragCtx& f, int lane, int wm, int wn) {
#pragma unroll
    for (int mt = 0; mt < 4; mt++)
        f.a_row[mt] = wm * 64 + mt * 16 + (lane & 7) + ((lane >> 3) & 1) * 8;
#pragma unroll
    for (int np = 0; np < 4; np++)
        f.b_row[np] = wn * 64 + np * 16 + (lane & 7) + ((lane >> 4) & 1) * 8;
    f.ac = lane >> 4;
    f.bc = (lane >> 3) & 1;
}

__device__ __forceinline__ void compute_k32(uint32_t ab, uint32_t bb, const FragCtx& f,
                                            float acc[4][8][4]) {
#pragma unroll
    for (int ks = 0; ks < 2; ks++) {
        const int kb = ks * 2;
        uint32_t a[4][4];
#pragma unroll
        for (int mt = 0; mt < 4; mt++)
            ldsm4(a[mt], ab + SWZ(f.a_row[mt], kb + f.ac));
        uint32_t bf[4][4];
#pragma unroll
        for (int np = 0; np < 4; np++)
            ldsm4(bf[np], bb + SWZ(f.b_row[np], kb + f.bc));
#pragma unroll
        for (int mt = 0; mt < 4; mt++) {
#pragma unroll
            for (int np = 0; np < 4; np++) {
                mma_f16(acc[mt][np * 2 + 0], a[mt], bf[np][0], bf[np][1]);
                mma_f16(acc[mt][np * 2 + 1], a[mt], bf[np][2], bf[np][3]);
            }
        }
    }
}

// load one 128x32 subtile (row-major src, row stride ld halves); 128 threads, 4 cp each
__device__ __forceinline__ void load_sub(uint32_t dst, const __half* __restrict__ src, int ld) {
    const int r0 = threadIdx.x >> 2, c = threadIdx.x & 3;
#pragma unroll
    for (int p = 0; p < 4; p++) {
        const int r = r0 + p * 32;
        cpa16(dst + SWZ(r, c), src + (size_t)r * ld + c * 8);
    }
}

// ---------------- QKV: single-shot K=128, grid (6, 32, 24), 128 thr ----------------
__global__ void __launch_bounds__(128, 2) gemm_qkv_kernel() {
    extern __shared__ __align__(16) char dsm[];
    char* base = (char*)(((uintptr_t)dsm + 1023) & ~(uintptr_t)1023);
    const uint32_t sb = s2u(base);          // A subs: sb + t*8KB; B subs: sb+32KB + t*8KB

    const int tid  = threadIdx.x;
    const int lane = tid & 31;
    const int warp = tid >> 5;
    const int wm = warp & 1, wn = warp >> 1;
    const int gid = lane >> 2, tig = lane & 3;

    const int z = blockIdx.z, mat = z >> 3, blk = z & 7;
    const __half* W = (mat == 0) ? g_wqt : (mat == 1) ? g_wkt : g_wvt;
    __half*       O = (mat == 0) ? g_q   : (mat == 1) ? g_k   : g_v;
    const __half* A = g_xh + (size_t)blockIdx.y * 128 * DIMX + blk * BLKD;
    const __half* B = W + (size_t)blk * BLKD * INNER + (size_t)blockIdx.x * 128 * BLKD;
    __half*       C = O + (size_t)blockIdx.y * 128 * QKVROW + blk * INNER + blockIdx.x * 128;

    // one burst: whole 64KB (A: 4 subtiles, B: 4 subtiles)
#pragma unroll
    for (int t = 0; t < 4; t++) {
        load_sub(sb + t * SUB_BYTES,                 A + t * 32, DIMX);
        load_sub(sb + 4 * SUB_BYTES + t * SUB_BYTES, B + t * 32, BLKD);
    }
    cp_commit();

    FragCtx f;
    frag_init(f, lane, wm, wn);
    float acc[4][8][4];
#pragma unroll
    for (int mt = 0; mt < 4; mt++)
#pragma unroll
        for (int nt = 0; nt < 8; nt++)
#pragma unroll
            for (int e = 0; e < 4; e++) acc[mt][nt][e] = 0.f;

    cp_wait<0>();
    __syncthreads();

#pragma unroll
    for (int t = 0; t < 4; t++)
        compute_k32(sb + t * SUB_BYTES, sb + (4 + t) * SUB_BYTES, f, acc);

    // epilogue (half out)
#pragma unroll
    for (int mt = 0; mt < 4; mt++) {
#pragma unroll
        for (int nt = 0; nt < 8; nt++) {
            int r  = wm * 64 + mt * 16 + gid;
            int cn = wn * 64 + nt * 8 + tig * 2;
            *(__half2*)(C + (size_t)r * QKVROW + cn) =
                __floats2half2_rn(acc[mt][nt][0], acc[mt][nt][1]);
            *(__half2*)(C + (size_t)(r + 8) * QKVROW + cn) =
                __floats2half2_rn(acc[mt][nt][2], acc[mt][nt][3]);
        }
    }
}

// ---------------- output projection: K=768 as 12 k64 chunks, 2-stage ring ----------
// grid (32, 8), 128 threads, 64KB smem -> 2 CTAs/SM.
__global__ void __launch_bounds__(128, 2) gemm_f_kernel(float* __restrict__ out) {
    extern __shared__ __align__(16) char dsm[];
    char* base = (char*)(((uintptr_t)dsm + 1023) & ~(uintptr_t)1023);
    const uint32_t sb = s2u(base);
    // stage s (0..1): A subs at sb + s*32KB + {0,8KB}; B subs at +16KB + {0,8KB}

    const int tid  = threadIdx.x;
    const int lane = tid & 31;
    const int warp = tid >> 5;
    const int wm = warp & 1, wn = warp >> 1;
    const int gid = lane >> 2, tig = lane & 3;

    const int blk = blockIdx.y;
    const __half* A = g_att + (size_t)blockIdx.x * 128 * QKVROW + blk * INNER;
    const __half* B = g_wft + (size_t)blk * BLKD * INNER;
    float*        C = out + (size_t)blockIdx.x * 128 * DIMX + blk * BLKD;

#define LOAD_CHUNK(c, s)                                                           \
    do {                                                                           \
        const uint32_t st = sb + (uint32_t)(s) * (4 * SUB_BYTES);                  \
        load_sub(st,                 A + (c) * 64,      QKVROW);                   \
        load_sub(st + SUB_BYTES,     A + (c) * 64 + 32, QKVROW);                   \
        load_sub(st + 2 * SUB_BYTES, B + (c) * 64,      INNER);                    \
        load_sub(st + 3 * SUB_BYTES, B + (c) * 64 + 32, INNER);                    \
        cp_commit();                                                               \
    } while (0)

    FragCtx f;
    frag_init(f, lane, wm, wn);
    float acc[4][8][4];
#pragma unroll
    for (int mt = 0; mt < 4; mt++)
#pragma unroll
        for (int nt = 0; nt < 8; nt++)
#pragma unroll
            for (int e = 0; e < 4; e++) acc[mt][nt][e] = 0.f;

    LOAD_CHUNK(0, 0);

    for (int t = 0; t < 12; t++) {
        if (t + 1 < 12) { LOAD_CHUNK(t + 1, (t + 1) & 1); cp_wait<1>(); }
        else            { cp_wait<0>(); }
        __syncthreads();

        const uint32_t st = sb + (uint32_t)(t & 1) * (4 * SUB_BYTES);
        compute_k32(st,             st + 2 * SUB_BYTES, f, acc);
        compute_k32(st + SUB_BYTES, st + 3 * SUB_BYTES, f, acc);
        __syncthreads();
    }
#undef LOAD_CHUNK

    // epilogue (float out)
#pragma unroll
    for (int mt = 0; mt < 4; mt++) {
#pragma unroll
        for (int nt = 0; nt < 8; nt++) {
            int r  = wm * 64 + mt * 16 + gid;
            int cn = wn * 64 + nt * 8 + tig * 2;
            *(float2*)(C + (size_t)r * DIMX + cn) =
                make_float2(acc[mt][nt][0], acc[mt][nt][1]);
            *(float2*)(C + (size_t)(r + 8) * DIMX + cn) =
                make_float2(acc[mt][nt][2], acc[mt][nt][3]);
        }
    }
}

// ---------------- attention: 1 CTA per token, 1 warp per head ----------------
__global__ void __launch_bounds__(384) attn_kernel(float* __restrict__ smean) {
    const int t    = blockIdx.x;
    const int h    = threadIdx.x >> 5;
    const int lane = threadIdx.x & 31;

    __shared__ float sm[NHEAD][64];

    const size_t base = (size_t)t * QKVROW + h * HDIM;
    float2 q[8], k[8], v[8];
#pragma unroll
    for (int j = 0; j < 8; j++) {
        q[j] = __half22float2(((const __half2*)(g_q + base + j * INNER))[lane]);
        k[j] = __half22float2(((const __half2*)(g_k + base + j * INNER))[lane]);
        v[j] = __half22float2(((const __half2*)(g_v + base + j * INNER))[lane]);
    }

    float own0 = 0.f, own1 = 0.f;
#pragma unroll
    for (int i = 0; i < 8; i++) {
#pragma unroll
        for (int j = 0; j < 8; j++) {
            float p = q[i].x * k[j].x + q[i].y * k[j].y;
#pragma unroll
            for (int m = 16; m > 0; m >>= 1)
                p += __shfl_xor_sync(0xFFFFFFFFu, p, m);
            const int f = i * 8 + j;
            if (f < 32) { if (lane == f)        own0 = p; }
            else        { if (lane == (f & 31)) own1 = p; }
        }
    }
    own0 *= SCALE;
    own1 *= SCALE;

    float m0 = own0, m1 = own1;
#pragma unroll
    for (int m = 4; m >= 1; m >>= 1) {
        m0 = fmaxf(m0, __shfl_xor_sync(0xFFFFFFFFu, m0, m));
        m1 = fmaxf(m1, __shfl_xor_sync(0xFFFFFFFFu, m1, m));
    }
    float e0 = expf(own0 - m0), e1 = expf(own1 - m1);
    float s0 = e0, s1 = e1;
#pragma unroll
    for (int m = 4; m >= 1; m >>= 1) {
        s0 += __shfl_xor_sync(0xFFFFFFFFu, s0, m);
        s1 += __shfl_xor_sync(0xFFFFFFFFu, s1, m);
    }
    const float a0 = e0 / s0;
    const float a1 = e1 / s1;

    sm[h][lane]      = a0;
    sm[h][lane + 32] = a1;

    float2 acc[8];
#pragma unroll
    for (int i = 0; i < 8; i++) acc[i] = make_float2(0.f, 0.f);
#pragma unroll
    for (int i = 0; i < 8; i++) {
#pragma unroll
        for (int j = 0; j < 8; j++) {
            const int f = i * 8 + j;
            float aij = __shfl_sync(0xFFFFFFFFu, (f < 32) ? a0 : a1, f & 31);
            acc[i].x = fmaf(aij, v[j].x, acc[i].x);
            acc[i].y = fmaf(aij, v[j].y, acc[i].y);
        }
    }
#pragma unroll
    for (int i = 0; i < 8; i++) {
        *(__half2*)(g_att + (size_t)t * QKVROW + i * INNER + h * HDIM + 2 * lane) =
            __floats2half2_rn(acc[i].x, acc[i].y);
    }

    __syncthreads();
    if (smean != nullptr && threadIdx.x < 64) {
        float s = 0.f;
#pragma unroll
        for (int hh = 0; hh < NHEAD; hh++) s += sm[hh][threadIdx.x];
        smean[(size_t)t * 64 + threadIdx.x] = s * (1.0f / 12.0f);
    }
}

// ---------------- launch ----------------
extern "C" void kernel_launch(void* const* d_in, const int* in_sizes, int n_in,
                              void* d_out, int out_size) {
    const float* x  = (const float*)d_in[0];
    const float* Wq = (const float*)d_in[1];
    const float* Wk = (const float*)d_in[2];
    const float* Wv = (const float*)d_in[3];
    const float* Wf = (const float*)d_in[4];
    float* out = (float*)d_out;

    cudaFuncSetAttribute(gemm_qkv_kernel, cudaFuncAttributeMaxDynamicSharedMemorySize, QKV_DSM);
    cudaFuncSetAttribute(gemm_f_kernel,   cudaFuncAttributeMaxDynamicSharedMemorySize, F_DSM);

    conv_x_kernel<<<SEQB * DIMX / 4 / 256, 256>>>(x);
    transpose_qkv_kernel<<<dim3(INNER / 32, BLKD / 32, 24), 256>>>(Wq, Wk, Wv);
    transpose_f_kernel<<<dim3(BLKD / 32, INNER / 32, NBLK), 256>>>(Wf);

    gemm_qkv_kernel<<<dim3(6, 32, 24), 128, QKV_DSM>>>();

    float* smean = (out_size >= SEQB * DIMX + SEQB * 64) ? (out + (size_t)SEQB * DIMX)
                                                         : nullptr;
    attn_kernel<<<SEQB, 384>>>(smean);

    gemm_f_kernel<<<dim3(32, NBLK), 128, F_DSM>>>(out);
}

// round 9
// speedup vs baseline: 2.1395x; 1.1310x over previous
#include <cuda_runtime.h>
#include <cuda_fp16.h>
#include <cstdint>

// Problem constants
#define SEQB   4096
#define DIMX   1024
#define NBLK   8
#define BLKD   128
#define NHEAD  12
#define HDIM   64
#define INNER  768
#define QKVROW (NBLK*INNER)        // 6144
#define WELEM  (NBLK*BLKD*INNER)   // 786432
#define SCALE  0.125f

// 128x32-half subtile (8KB), 64B rows, XOR-swizzled at 16B granularity
#define SUB_BYTES 8192
#define SWZ(row, ch) (((row) * 64) + ((((ch) ^ (((row) >> 1) & 3)) << 4)))

// epilogue stage layouts (rotation keeps smem banks conflict-light, rows dense)
#define SROT(row, u) (((row) * 256) + (((((u) + (row)) & 15)) << 4))   // half tile, 32KB
#define FROT(row, u) (((row) * 512) + (((((u) + (row)) & 31)) << 4))   // fp32 tile, 64KB

#define QKV_DSM (12*SUB_BYTES + 1024)   // A(32KB) + 2 B buffers(64KB)
#define F_DSM   (8*SUB_BYTES + 1024)    // 2 stages x (2A + 2B); stage reuses all 64KB

// ---------------- scratch (device globals; allocation is forbidden) ----------------
__device__ __align__(16) __half g_xh [SEQB*DIMX];
__device__ __align__(16) __half g_wqt[WELEM];         // [blk][n=INNER][k=BLKD]
__device__ __align__(16) __half g_wkt[WELEM];
__device__ __align__(16) __half g_wvt[WELEM];
__device__ __align__(16) __half g_wft[WELEM];         // [blk][n=BLKD][k=INNER]
__device__ __align__(16) __half g_q  [SEQB*QKVROW];
__device__ __align__(16) __half g_k  [SEQB*QKVROW];
__device__ __align__(16) __half g_v  [SEQB*QKVROW];
__device__ __align__(16) __half g_att[SEQB*QKVROW];

// ---------------- helpers ----------------
__device__ __forceinline__ void mma_f16(float c[4], const uint32_t a[4],
                                        uint32_t b0, uint32_t b1) {
    asm volatile(
        "mma.sync.aligned.m16n8k16.row.col.f32.f16.f16.f32 "
        "{%0,%1,%2,%3}, {%4,%5,%6,%7}, {%8,%9}, {%0,%1,%2,%3};\n"
        : "+f"(c[0]), "+f"(c[1]), "+f"(c[2]), "+f"(c[3])
        : "r"(a[0]), "r"(a[1]), "r"(a[2]), "r"(a[3]), "r"(b0), "r"(b1));
}

__device__ __forceinline__ void ldsm4(uint32_t r[4], uint32_t addr) {
    asm volatile("ldmatrix.sync.aligned.m8n8.x4.shared.b16 {%0,%1,%2,%3}, [%4];"
                 : "=r"(r[0]), "=r"(r[1]), "=r"(r[2]), "=r"(r[3]) : "r"(addr));
}

__device__ __forceinline__ void stsm4(uint32_t addr, uint32_t v0, uint32_t v1,
                                      uint32_t v2, uint32_t v3) {
    asm volatile("stmatrix.sync.aligned.m8n8.x4.shared.b16 [%0], {%1,%2,%3,%4};"
                 :: "r"(addr), "r"(v0), "r"(v1), "r"(v2), "r"(v3) : "memory");
}

__device__ __forceinline__ void lds128(uint4& v, uint32_t addr) {
    asm volatile("ld.shared.v4.u32 {%0,%1,%2,%3}, [%4];"
                 : "=r"(v.x), "=r"(v.y), "=r"(v.z), "=r"(v.w) : "r"(addr));
}

__device__ __forceinline__ void sts64(uint32_t addr, float a, float b) {
    asm volatile("st.shared.v2.f32 [%0], {%1,%2};" :: "r"(addr), "f"(a), "f"(b) : "memory");
}

__device__ __forceinline__ uint32_t pack_h2(float a, float b) {
    __half2 h = __floats2half2_rn(a, b);
    return *(uint32_t*)&h;
}

__device__ __forceinline__ void cpa16(uint32_t smem_dst, const __half* gmem_src) {
    asm volatile("cp.async.ca.shared.global [%0], [%1], 16;\n" :: "r"(smem_dst), "l"(gmem_src));
}
__device__ __forceinline__ void cp_commit() { asm volatile("cp.async.commit_group;\n"); }
template <int N>
__device__ __forceinline__ void cp_wait() { asm volatile("cp.async.wait_group %0;\n" :: "n"(N)); }

__device__ __forceinline__ uint32_t s2u(const void* p) {
    return (uint32_t)__cvta_generic_to_shared(p);
}

// ---------------- prep: x -> half ----------------
__global__ void conv_x_kernel(const float* __restrict__ x) {
    int i = (blockIdx.x * blockDim.x + threadIdx.x) * 4;
    float4 v = *(const float4*)(x + i);
    __half2* o = (__half2*)(g_xh + i);
    o[0] = __floats2half2_rn(v.x, v.y);
    o[1] = __floats2half2_rn(v.z, v.w);
}

// ---------------- prep: transpose weights to [blk][n][k] half ----------------
__global__ void transpose_qkv_kernel(const float* __restrict__ wq,
                                     const float* __restrict__ wk,
                                     const float* __restrict__ wv) {
    __shared__ float tile[32][33];
    const int mat = blockIdx.z >> 3;
    const int blk = blockIdx.z & 7;
    const float* W = (mat == 0) ? wq : (mat == 1) ? wk : wv;
    __half* O      = (mat == 0) ? g_wqt : (mat == 1) ? g_wkt : g_wvt;
    const float* Wb = W + (size_t)blk * BLKD * INNER;   // [k=BLKD][n=INNER]
    __half* Ob      = O + (size_t)blk * BLKD * INNER;   // [n=INNER][k=BLKD]
    int n0 = blockIdx.x * 32, k0 = blockIdx.y * 32;
    int tx = threadIdx.x & 31, ty0 = threadIdx.x >> 5;
#pragma unroll
    for (int p = 0; p < 4; p++) {
        int ty = ty0 + p * 8;
        tile[ty][tx] = Wb[(size_t)(k0 + ty) * INNER + n0 + tx];
    }
    __syncthreads();
#pragma unroll
    for (int p = 0; p < 4; p++) {
        int ty = ty0 + p * 8;
        Ob[(size_t)(n0 + ty) * BLKD + k0 + tx] = __float2half_rn(tile[tx][ty]);
    }
}

__global__ void transpose_f_kernel(const float* __restrict__ wf) {
    __shared__ float tile[32][33];
    const int blk = blockIdx.z;
    const float* Wb = wf + (size_t)blk * INNER * BLKD;    // [k=INNER][n=BLKD]
    __half* Ob      = g_wft + (size_t)blk * INNER * BLKD; // [n=BLKD][k=INNER]
    int n0 = blockIdx.x * 32, k0 = blockIdx.y * 32;
    int tx = threadIdx.x & 31, ty0 = threadIdx.x >> 5;
#pragma unroll
    for (int p = 0; p < 4; p++) {
        int ty = ty0 + p * 8;
        tile[ty][tx] = Wb[(size_t)(k0 + ty) * BLKD + n0 + tx];
    }
    __syncthreads();
#pragma unroll
    for (int p = 0; p < 4; p++) {
        int ty = ty0 + p * 8;
        Ob[(size_t)(n0 + ty) * INNER + k0 + tx] = __float2half_rn(tile[tx][ty]);
    }
}

// ---------------- mma core: warp tile 64(M) x 64(N), CTA 128x128, 4 warps ---------
struct FragCtx {
    int a_row[4];
    int b_row[4];
    int ac, bc;
};

__device__ __forceinline__ void frag_init(FragCtx& f, int lane, int wm, int wn) {
#pragma unroll
    for (int mt = 0; mt < 4; mt++)
        f.a_row[mt] = wm * 64 + mt * 16 + (lane & 7) + ((lane >> 3) & 1) * 8;
#pragma unroll
    for (int np = 0; np < 4; np++)
        f.b_row[np] = wn * 64 + np * 16 + (lane & 7) + ((lane >> 4) & 1) * 8;
    f.ac = lane >> 4;
    f.bc = (lane >> 3) & 1;
}

__device__ __forceinline__ void compute_k32(uint32_t ab, uint32_t bb, const FragCtx& f,
                                            float acc[4][8][4]) {
#pragma unroll
    for (int ks = 0; ks < 2; ks++) {
        const int kb = ks * 2;
        uint32_t a[4][4];
#pragma unroll
        for (int mt = 0; mt < 4; mt++)
            ldsm4(a[mt], ab + SWZ(f.a_row[mt], kb + f.ac));
        uint32_t bf[4][4];
#pragma unroll
        for (int np = 0; np < 4; np++)
            ldsm4(bf[np], bb + SWZ(f.b_row[np], kb + f.bc));
#pragma unroll
        for (int mt = 0; mt < 4; mt++) {
#pragma unroll
            for (int np = 0; np < 4; np++) {
                mma_f16(acc[mt][np * 2 + 0], a[mt], bf[np][0], bf[np][1]);
                mma_f16(acc[mt][np * 2 + 1], a[mt], bf[np][2], bf[np][3]);
            }
        }
    }
}

// load one 128x32 subtile (row-major src, row stride ld halves); 128 threads, 4 cp each
__device__ __forceinline__ void load_sub(uint32_t dst, const __half* __restrict__ src, int ld) {
    const int r0 = threadIdx.x >> 2, c = threadIdx.x & 3;
#pragma unroll
    for (int p = 0; p < 4; p++) {
        const int r = r0 + p * 32;
        cpa16(dst + SWZ(r, c), src + (size_t)r * ld + c * 8);
    }
}

// ---------------- staged half epilogue: stmatrix -> rotated stage -> STG.128 -------
__device__ __forceinline__ void epilogue_half(const float acc[4][8][4], __half* __restrict__ C,
                                              int ldc, uint32_t stage, int wm, int wn,
                                              int lane, int tid) {
    const int t4 = lane >> 3, rr = lane & 7;
#pragma unroll
    for (int mt = 0; mt < 4; mt++) {
#pragma unroll
        for (int ntp = 0; ntp < 4; ntp++) {
            int row = wm * 64 + mt * 16 + (t4 & 1) * 8 + rr;
            int u   = wn * 8 + ntp * 2 + (t4 >> 1);
            uint32_t v0 = pack_h2(acc[mt][2 * ntp][0],     acc[mt][2 * ntp][1]);
            uint32_t v1 = pack_h2(acc[mt][2 * ntp][2],     acc[mt][2 * ntp][3]);
            uint32_t v2 = pack_h2(acc[mt][2 * ntp + 1][0], acc[mt][2 * ntp + 1][1]);
            uint32_t v3 = pack_h2(acc[mt][2 * ntp + 1][2], acc[mt][2 * ntp + 1][3]);
            stsm4(stage + SROT(row, u), v0, v1, v2, v3);
        }
    }
    __syncthreads();
#pragma unroll
    for (int p = 0; p < 16; p++) {
        int row = (tid >> 4) + p * 8;
        int u   = tid & 15;
        uint4 val;
        lds128(val, stage + SROT(row, u));
        *(uint4*)(C + (size_t)row * ldc + u * 8) = val;
    }
}

// ---------------- QKV: fused q/k/v, A loaded once, B ring. grid (6, 32, 8) --------
__global__ void __launch_bounds__(128, 2) gemm_qkv_kernel() {
    extern __shared__ __align__(16) char dsm[];
    char* base = (char*)(((uintptr_t)dsm + 1023) & ~(uintptr_t)1023);
    const uint32_t Asb = s2u(base);
    const uint32_t Bsb0 = Asb + 4 * SUB_BYTES;
    const uint32_t Bsb1 = Asb + 8 * SUB_BYTES;

    const int tid  = threadIdx.x;
    const int lane = tid & 31;
    const int warp = tid >> 5;
    const int wm = warp & 1, wn = warp >> 1;

    const int blk = blockIdx.z;
    const size_t woff = (size_t)blk * BLKD * INNER + (size_t)blockIdx.x * 128 * BLKD;
    const size_t coff = (size_t)blockIdx.y * 128 * QKVROW + blk * INNER + blockIdx.x * 128;
    const __half* A  = g_xh + (size_t)blockIdx.y * 128 * DIMX + blk * BLKD;
    const __half* Bq = g_wqt + woff;
    const __half* Bk = g_wkt + woff;
    const __half* Bv = g_wvt + woff;
    __half* Cq = g_q + coff;
    __half* Ck = g_k + coff;
    __half* Cv = g_v + coff;

    // group 1: A + B(q); group 2: B(k)
#pragma unroll
    for (int t = 0; t < 4; t++) {
        load_sub(Asb + t * SUB_BYTES,  A  + t * 32, DIMX);
        load_sub(Bsb0 + t * SUB_BYTES, Bq + t * 32, BLKD);
    }
    cp_commit();
#pragma unroll
    for (int t = 0; t < 4; t++)
        load_sub(Bsb1 + t * SUB_BYTES, Bk + t * 32, BLKD);
    cp_commit();

    FragCtx f;
    frag_init(f, lane, wm, wn);
    float acc[4][8][4];

    // ---- q ----
#pragma unroll
    for (int mt = 0; mt < 4; mt++)
#pragma unroll
        for (int nt = 0; nt < 8; nt++)
#pragma unroll
            for (int e = 0; e < 4; e++) acc[mt][nt][e] = 0.f;
    cp_wait<1>();
    __syncthreads();
#pragma unroll
    for (int t = 0; t < 4; t++)
        compute_k32(Asb + t * SUB_BYTES, Bsb0 + t * SUB_BYTES, f, acc);
    __syncthreads();
    epilogue_half(acc, Cq, QKVROW, Bsb0, wm, wn, lane, tid);
    __syncthreads();
    // group 3: B(v) into buffer 0 (q stage fully drained by the sync above)
#pragma unroll
    for (int t = 0; t < 4; t++)
        load_sub(Bsb0 + t * SUB_BYTES, Bv + t * 32, BLKD);
    cp_commit();

    // ---- k ----
#pragma unroll
    for (int mt = 0; mt < 4; mt++)
#pragma unroll
        for (int nt = 0; nt < 8; nt++)
#pragma unroll
            for (int e = 0; e < 4; e++) acc[mt][nt][e] = 0.f;
    cp_wait<1>();
    __syncthreads();
#pragma unroll
    for (int t = 0; t < 4; t++)
        compute_k32(Asb + t * SUB_BYTES, Bsb1 + t * SUB_BYTES, f, acc);
    __syncthreads();
    epilogue_half(acc, Ck, QKVROW, Bsb1, wm, wn, lane, tid);

    // ---- v ----
#pragma unroll
    for (int mt = 0; mt < 4; mt++)
#pragma unroll
        for (int nt = 0; nt < 8; nt++)
#pragma unroll
            for (int e = 0; e < 4; e++) acc[mt][nt][e] = 0.f;
    cp_wait<0>();
    __syncthreads();
#pragma unroll
    for (int t = 0; t < 4; t++)
        compute_k32(Asb + t * SUB_BYTES, Bsb0 + t * SUB_BYTES, f, acc);
    __syncthreads();
    epilogue_half(acc, Cv, QKVROW, Bsb0, wm, wn, lane, tid);
}

// ---------------- output projection: K=768 as 12 k64 chunks, 2-stage ring ----------
// grid (32, 8), 128 threads, 64KB smem -> 2 CTAs/SM.
__global__ void __launch_bounds__(128, 2) gemm_f_kernel(float* __restrict__ out) {
    extern __shared__ __align__(16) char dsm[];
    char* base = (char*)(((uintptr_t)dsm + 1023) & ~(uintptr_t)1023);
    const uint32_t sb = s2u(base);

    const int tid  = threadIdx.x;
    const int lane = tid & 31;
    const int warp = tid >> 5;
    const int wm = warp & 1, wn = warp >> 1;
    const int gid = lane >> 2, tig = lane & 3;

    const int blk = blockIdx.y;
    const __half* A = g_att + (size_t)blockIdx.x * 128 * QKVROW + blk * INNER;
    const __half* B = g_wft + (size_t)blk * BLKD * INNER;
    float*        C = out + (size_t)blockIdx.x * 128 * DIMX + blk * BLKD;

#define LOAD_CHUNK(c, s)                                                           \
    do {                                                                           \
        const uint32_t st = sb + (uint32_t)(s) * (4 * SUB_BYTES);                  \
        load_sub(st,                 A + (c) * 64,      QKVROW);                   \
        load_sub(st + SUB_BYTES,     A + (c) * 64 + 32, QKVROW);                   \
        load_sub(st + 2 * SUB_BYTES, B + (c) * 64,      INNER);                    \
        load_sub(st + 3 * SUB_BYTES, B + (c) * 64 + 32, INNER);                    \
        cp_commit();                                                               \
    } while (0)

    FragCtx f;
    frag_init(f, lane, wm, wn);
    float acc[4][8][4];
#pragma unroll
    for (int mt = 0; mt < 4; mt++)
#pragma unroll
        for (int nt = 0; nt < 8; nt++)
#pragma unroll
            for (int e = 0; e < 4; e++) acc[mt][nt][e] = 0.f;

    LOAD_CHUNK(0, 0);

    for (int t = 0; t < 12; t++) {
        if (t + 1 < 12) { LOAD_CHUNK(t + 1, (t + 1) & 1); cp_wait<1>(); }
        else            { cp_wait<0>(); }
        __syncthreads();

        const uint32_t st = sb + (uint32_t)(t & 1) * (4 * SUB_BYTES);
        compute_k32(st,             st + 2 * SUB_BYTES, f, acc);
        compute_k32(st + SUB_BYTES, st + 3 * SUB_BYTES, f, acc);
        __syncthreads();
    }
#undef LOAD_CHUNK

    // staged fp32 epilogue: STS.64 -> rotated 64KB stage -> coalesced STG.128
#pragma unroll
    for (int mt = 0; mt < 4; mt++) {
#pragma unroll
        for (int nt = 0; nt < 8; nt++) {
            int r0  = wm * 64 + mt * 16 + gid;
            int u   = wn * 16 + nt * 2 + (tig >> 1);
            int off = (tig & 1) * 8;
            sts64(sb + FROT(r0, u) + off,     acc[mt][nt][0], acc[mt][nt][1]);
            sts64(sb + FROT(r0 + 8, u) + off, acc[mt][nt][2], acc[mt][nt][3]);
        }
    }
    __syncthreads();
#pragma unroll
    for (int p = 0; p < 32; p++) {
        int row = (tid >> 5) + p * 4;
        int u   = tid & 31;
        uint4 val;
        lds128(val, sb + FROT(row, u));
        *(uint4*)(C + (size_t)row * DIMX + u * 4) = val;
    }
}

// ---------------- attention: 1 CTA per token, 1 warp per head ----------------
__global__ void __launch_bounds__(384) attn_kernel(float* __restrict__ smean) {
    const int t    = blockIdx.x;
    const int h    = threadIdx.x >> 5;
    const int lane = threadIdx.x & 31;

    __shared__ float sm[NHEAD][64];

    const size_t base = (size_t)t * QKVROW + h * HDIM;
    float2 q[8], k[8], v[8];
#pragma unroll
    for (int j = 0; j < 8; j++) {
        q[j] = __half22float2(((const __half2*)(g_q + base + j * INNER))[lane]);
        k[j] = __half22float2(((const __half2*)(g_k + base + j * INNER))[lane]);
        v[j] = __half22float2(((const __half2*)(g_v + base + j * INNER))[lane]);
    }

    float own0 = 0.f, own1 = 0.f;
#pragma unroll
    for (int i = 0; i < 8; i++) {
#pragma unroll
        for (int j = 0; j < 8; j++) {
            float p = q[i].x * k[j].x + q[i].y * k[j].y;
#pragma unroll
            for (int m = 16; m > 0; m >>= 1)
                p += __shfl_xor_sync(0xFFFFFFFFu, p, m);
            const int f = i * 8 + j;
            if (f < 32) { if (lane == f)        own0 = p; }
            else        { if (lane == (f & 31)) own1 = p; }
        }
    }
    own0 *= SCALE;
    own1 *= SCALE;

    float m0 = own0, m1 = own1;
#pragma unroll
    for (int m = 4; m >= 1; m >>= 1) {
        m0 = fmaxf(m0, __shfl_xor_sync(0xFFFFFFFFu, m0, m));
        m1 = fmaxf(m1, __shfl_xor_sync(0xFFFFFFFFu, m1, m));
    }
    float e0 = expf(own0 - m0), e1 = expf(own1 - m1);
    float s0 = e0, s1 = e1;
#pragma unroll
    for (int m = 4; m >= 1; m >>= 1) {
        s0 += __shfl_xor_sync(0xFFFFFFFFu, s0, m);
        s1 += __shfl_xor_sync(0xFFFFFFFFu, s1, m);
    }
    const float a0 = e0 / s0;
    const float a1 = e1 / s1;

    sm[h][lane]      = a0;
    sm[h][lane + 32] = a1;

    float2 acc[8];
#pragma unroll
    for (int i = 0; i < 8; i++) acc[i] = make_float2(0.f, 0.f);
#pragma unroll
    for (int i = 0; i < 8; i++) {
#pragma unroll
        for (int j = 0; j < 8; j++) {
            const int f = i * 8 + j;
            float aij = __shfl_sync(0xFFFFFFFFu, (f < 32) ? a0 : a1, f & 31);
            acc[i].x = fmaf(aij, v[j].x, acc[i].x);
            acc[i].y = fmaf(aij, v[j].y, acc[i].y);
        }
    }
#pragma unroll
    for (int i = 0; i < 8; i++) {
        *(__half2*)(g_att + (size_t)t * QKVROW + i * INNER + h * HDIM + 2 * lane) =
            __floats2half2_rn(acc[i].x, acc[i].y);
    }

    __syncthreads();
    if (smean != nullptr && threadIdx.x < 64) {
        float s = 0.f;
#pragma unroll
        for (int hh = 0; hh < NHEAD; hh++) s += sm[hh][threadIdx.x];
        smean[(size_t)t * 64 + threadIdx.x] = s * (1.0f / 12.0f);
    }
}

// ---------------- launch ----------------
extern "C" void kernel_launch(void* const* d_in, const int* in_sizes, int n_in,
                              void* d_out, int out_size) {
    const float* x  = (const float*)d_in[0];
    const float* Wq = (const float*)d_in[1];
    const float* Wk = (const float*)d_in[2];
    const float* Wv = (const float*)d_in[3];
    const float* Wf = (const float*)d_in[4];
    float* out = (float*)d_out;

    cudaFuncSetAttribute(gemm_qkv_kernel, cudaFuncAttributeMaxDynamicSharedMemorySize, QKV_DSM);
    cudaFuncSetAttribute(gemm_f_kernel,   cudaFuncAttributeMaxDynamicSharedMemorySize, F_DSM);

    conv_x_kernel<<<SEQB * DIMX / 4 / 256, 256>>>(x);
    transpose_qkv_kernel<<<dim3(INNER / 32, BLKD / 32, 24), 256>>>(Wq, Wk, Wv);
    transpose_f_kernel<<<dim3(BLKD / 32, INNER / 32, NBLK), 256>>>(Wf);

    gemm_qkv_kernel<<<dim3(6, 32, 8), 128, QKV_DSM>>>();

    float* smean = (out_size >= SEQB * DIMX + SEQB * 64) ? (out + (size_t)SEQB * DIMX)
                                                         : nullptr;
    attn_kernel<<<SEQB, 384>>>(smean);

    gemm_f_kernel<<<dim3(32, NBLK), 128, F_DSM>>>(out);
}

// round 10
// speedup vs baseline: 2.4633x; 1.1513x over previous
#include <cuda_runtime.h>
#include <cuda_fp16.h>
#include <cstdint>

// Problem constants
#define SEQB   4096
#define DIMX   1024
#define NBLK   8
#define BLKD   128
#define NHEAD  12
#define HDIM   64
#define INNER  768
#define QKVROW (NBLK*INNER)        // 6144
#define WELEM  (NBLK*BLKD*INNER)   // 786432
#define SCALE  0.125f

// 128x32-half subtile (8KB), 64B rows, XOR-swizzled at 16B granularity
#define SUB_BYTES 8192
#define SWZ(row, ch) (((row) * 64) + ((((ch) ^ (((row) >> 1) & 3)) << 4)))

// epilogue stage layouts (rotation keeps smem banks conflict-light, rows dense)
#define SROT(row, u) (((row) * 256) + (((((u) + (row)) & 15)) << 4))   // half tile, 32KB
#define FROT(row, u) (((row) * 512) + (((((u) + (row)) & 31)) << 4))   // fp32 tile, 64KB

#define QKV_DSM (12*SUB_BYTES + 1024)   // A(32KB) + 2 B buffers(64KB)
#define F_DSM   (8*SUB_BYTES + 1024)    // 2 stages x (2A + 2B); stage reuses all 64KB

// ---------------- scratch (device globals; allocation is forbidden) ----------------
__device__ __align__(16) __half g_xh [SEQB*DIMX];
__device__ __align__(16) __half g_wqt[WELEM];         // [blk][n=INNER][k=BLKD]
__device__ __align__(16) __half g_wkt[WELEM];
__device__ __align__(16) __half g_wvt[WELEM];
__device__ __align__(16) __half g_wft[WELEM];         // [blk][n=BLKD][k=INNER]
__device__ __align__(16) __half g_q  [SEQB*QKVROW];
__device__ __align__(16) __half g_k  [SEQB*QKVROW];
__device__ __align__(16) __half g_v  [SEQB*QKVROW];
__device__ __align__(16) __half g_att[SEQB*QKVROW];

// ---------------- helpers ----------------
__device__ __forceinline__ void mma_f16(float c[4], const uint32_t a[4],
                                        uint32_t b0, uint32_t b1) {
    asm volatile(
        "mma.sync.aligned.m16n8k16.row.col.f32.f16.f16.f32 "
        "{%0,%1,%2,%3}, {%4,%5,%6,%7}, {%8,%9}, {%0,%1,%2,%3};\n"
        : "+f"(c[0]), "+f"(c[1]), "+f"(c[2]), "+f"(c[3])
        : "r"(a[0]), "r"(a[1]), "r"(a[2]), "r"(a[3]), "r"(b0), "r"(b1));
}

__device__ __forceinline__ void ldsm4(uint32_t r[4], uint32_t addr) {
    asm volatile("ldmatrix.sync.aligned.m8n8.x4.shared.b16 {%0,%1,%2,%3}, [%4];"
                 : "=r"(r[0]), "=r"(r[1]), "=r"(r[2]), "=r"(r[3]) : "r"(addr));
}

__device__ __forceinline__ void stsm4(uint32_t addr, uint32_t v0, uint32_t v1,
                                      uint32_t v2, uint32_t v3) {
    asm volatile("stmatrix.sync.aligned.m8n8.x4.shared.b16 [%0], {%1,%2,%3,%4};"
                 :: "r"(addr), "r"(v0), "r"(v1), "r"(v2), "r"(v3) : "memory");
}

__device__ __forceinline__ void lds128(uint4& v, uint32_t addr) {
    asm volatile("ld.shared.v4.u32 {%0,%1,%2,%3}, [%4];"
                 : "=r"(v.x), "=r"(v.y), "=r"(v.z), "=r"(v.w) : "r"(addr));
}

__device__ __forceinline__ void sts64(uint32_t addr, float a, float b) {
    asm volatile("st.shared.v2.f32 [%0], {%1,%2};" :: "r"(addr), "f"(a), "f"(b) : "memory");
}

__device__ __forceinline__ uint32_t pack_h2(float a, float b) {
    __half2 h = __floats2half2_rn(a, b);
    return *(uint32_t*)&h;
}

__device__ __forceinline__ void cpa16(uint32_t smem_dst, const __half* gmem_src) {
    asm volatile("cp.async.ca.shared.global [%0], [%1], 16;\n" :: "r"(smem_dst), "l"(gmem_src));
}
__device__ __forceinline__ void cp_commit() { asm volatile("cp.async.commit_group;\n"); }
template <int N>
__device__ __forceinline__ void cp_wait() { asm volatile("cp.async.wait_group %0;\n" :: "n"(N)); }

__device__ __forceinline__ uint32_t s2u(const void* p) {
    return (uint32_t)__cvta_generic_to_shared(p);
}

// ---------------- prep: x -> half ----------------
__global__ void conv_x_kernel(const float* __restrict__ x) {
    int i = (blockIdx.x * blockDim.x + threadIdx.x) * 4;
    float4 v = *(const float4*)(x + i);
    __half2* o = (__half2*)(g_xh + i);
    o[0] = __floats2half2_rn(v.x, v.y);
    o[1] = __floats2half2_rn(v.z, v.w);
}

// ---------------- prep: transpose weights to [blk][n][k] half ----------------
__global__ void transpose_qkv_kernel(const float* __restrict__ wq,
                                     const float* __restrict__ wk,
                                     const float* __restrict__ wv) {
    __shared__ float tile[32][33];
    const int mat = blockIdx.z >> 3;
    const int blk = blockIdx.z & 7;
    const float* W = (mat == 0) ? wq : (mat == 1) ? wk : wv;
    __half* O      = (mat == 0) ? g_wqt : (mat == 1) ? g_wkt : g_wvt;
    const float* Wb = W + (size_t)blk * BLKD * INNER;   // [k=BLKD][n=INNER]
    __half* Ob      = O + (size_t)blk * BLKD * INNER;   // [n=INNER][k=BLKD]
    int n0 = blockIdx.x * 32, k0 = blockIdx.y * 32;
    int tx = threadIdx.x & 31, ty0 = threadIdx.x >> 5;
#pragma unroll
    for (int p = 0; p < 4; p++) {
        int ty = ty0 + p * 8;
        tile[ty][tx] = Wb[(size_t)(k0 + ty) * INNER + n0 + tx];
    }
    __syncthreads();
#pragma unroll
    for (int p = 0; p < 4; p++) {
        int ty = ty0 + p * 8;
        Ob[(size_t)(n0 + ty) * BLKD + k0 + tx] = __float2half_rn(tile[tx][ty]);
    }
}

__global__ void transpose_f_kernel(const float* __restrict__ wf) {
    __shared__ float tile[32][33];
    const int blk = blockIdx.z;
    const float* Wb = wf + (size_t)blk * INNER * BLKD;    // [k=INNER][n=BLKD]
    __half* Ob      = g_wft + (size_t)blk * INNER * BLKD; // [n=BLKD][k=INNER]
    int n0 = blockIdx.x * 32, k0 = blockIdx.y * 32;
    int tx = threadIdx.x & 31, ty0 = threadIdx.x >> 5;
#pragma unroll
    for (int p = 0; p < 4; p++) {
        int ty = ty0 + p * 8;
        tile[ty][tx] = Wb[(size_t)(k0 + ty) * BLKD + n0 + tx];
    }
    __syncthreads();
#pragma unroll
    for (int p = 0; p < 4; p++) {
        int ty = ty0 + p * 8;
        Ob[(size_t)(n0 + ty) * INNER + k0 + tx] = __float2half_rn(tile[tx][ty]);
    }
}

// ---------------- mma core: warp tile 64(M) x 64(N), CTA 128x128, 4 warps ---------
struct FragCtx {
    int a_row[4];
    int b_row[4];
    int ac, bc;
};

__device__ __forceinline__ void frag_init(FragCtx& f, int lane, int wm, int wn) {
#pragma unroll
    for (int mt = 0; mt < 4; mt++)
        f.a_row[mt] = wm * 64 + mt * 16 + (lane & 7) + ((lane >> 3) & 1) * 8;
#pragma unroll
    for (int np = 0; np < 4; np++)
        f.b_row[np] = wn * 64 + np * 16 + (lane & 7) + ((lane >> 4) & 1) * 8;
    f.ac = lane >> 4;
    f.bc = (lane >> 3) & 1;
}

__device__ __forceinline__ void compute_k32(uint32_t ab, uint32_t bb, const FragCtx& f,
                                            float acc[4][8][4]) {
#pragma unroll
    for (int ks = 0; ks < 2; ks++) {
        const int kb = ks * 2;
        uint32_t a[4][4];
#pragma unroll
        for (int mt = 0; mt < 4; mt++)
            ldsm4(a[mt], ab + SWZ(f.a_row[mt], kb + f.ac));
        uint32_t bf[4][4];
#pragma unroll
        for (int np = 0; np < 4; np++)
            ldsm4(bf[np], bb + SWZ(f.b_row[np], kb + f.bc));
#pragma unroll
        for (int mt = 0; mt < 4; mt++) {
#pragma unroll
            for (int np = 0; np < 4; np++) {
                mma_f16(acc[mt][np * 2 + 0], a[mt], bf[np][0], bf[np][1]);
                mma_f16(acc[mt][np * 2 + 1], a[mt], bf[np][2], bf[np][3]);
            }
        }
    }
}

// load one 128x32 subtile (row-major src, row stride ld halves); 128 threads, 4 cp each
__device__ __forceinline__ void load_sub(uint32_t dst, const __half* __restrict__ src, int ld) {
    const int r0 = threadIdx.x >> 2, c = threadIdx.x & 3;
#pragma unroll
    for (int p = 0; p < 4; p++) {
        const int r = r0 + p * 32;
        cpa16(dst + SWZ(r, c), src + (size_t)r * ld + c * 8);
    }
}

// ---------------- staged half epilogue: stmatrix -> rotated stage -> STG.128 -------
__device__ __forceinline__ void epilogue_half(const float acc[4][8][4], __half* __restrict__ C,
                                              int ldc, uint32_t stage, int wm, int wn,
                                              int lane, int tid) {
    const int t4 = lane >> 3, rr = lane & 7;
#pragma unroll
    for (int mt = 0; mt < 4; mt++) {
#pragma unroll
        for (int ntp = 0; ntp < 4; ntp++) {
            int row = wm * 64 + mt * 16 + (t4 & 1) * 8 + rr;
            int u   = wn * 8 + ntp * 2 + (t4 >> 1);
            uint32_t v0 = pack_h2(acc[mt][2 * ntp][0],     acc[mt][2 * ntp][1]);
            uint32_t v1 = pack_h2(acc[mt][2 * ntp][2],     acc[mt][2 * ntp][3]);
            uint32_t v2 = pack_h2(acc[mt][2 * ntp + 1][0], acc[mt][2 * ntp + 1][1]);
            uint32_t v3 = pack_h2(acc[mt][2 * ntp + 1][2], acc[mt][2 * ntp + 1][3]);
            stsm4(stage + SROT(row, u), v0, v1, v2, v3);
        }
    }
    __syncthreads();
#pragma unroll
    for (int p = 0; p < 16; p++) {
        int row = (tid >> 4) + p * 8;
        int u   = tid & 15;
        uint4 val;
        lds128(val, stage + SROT(row, u));
        *(uint4*)(C + (size_t)row * ldc + u * 8) = val;
    }
}

// ---------------- QKV: fused q/k/v, A loaded once, B ring. grid (6, 32, 8) --------
__global__ void __launch_bounds__(128, 2) gemm_qkv_kernel() {
    extern __shared__ __align__(16) char dsm[];
    char* base = (char*)(((uintptr_t)dsm + 1023) & ~(uintptr_t)1023);
    const uint32_t Asb = s2u(base);
    const uint32_t Bsb0 = Asb + 4 * SUB_BYTES;
    const uint32_t Bsb1 = Asb + 8 * SUB_BYTES;

    const int tid  = threadIdx.x;
    const int lane = tid & 31;
    const int warp = tid >> 5;
    const int wm = warp & 1, wn = warp >> 1;

    const int blk = blockIdx.z;
    const size_t woff = (size_t)blk * BLKD * INNER + (size_t)blockIdx.x * 128 * BLKD;
    const size_t coff = (size_t)blockIdx.y * 128 * QKVROW + blk * INNER + blockIdx.x * 128;
    const __half* A  = g_xh + (size_t)blockIdx.y * 128 * DIMX + blk * BLKD;
    const __half* Bq = g_wqt + woff;
    const __half* Bk = g_wkt + woff;
    const __half* Bv = g_wvt + woff;
    __half* Cq = g_q + coff;
    __half* Ck = g_k + coff;
    __half* Cv = g_v + coff;

    // group 1: A + B(q); group 2: B(k)
#pragma unroll
    for (int t = 0; t < 4; t++) {
        load_sub(Asb + t * SUB_BYTES,  A  + t * 32, DIMX);
        load_sub(Bsb0 + t * SUB_BYTES, Bq + t * 32, BLKD);
    }
    cp_commit();
#pragma unroll
    for (int t = 0; t < 4; t++)
        load_sub(Bsb1 + t * SUB_BYTES, Bk + t * 32, BLKD);
    cp_commit();

    FragCtx f;
    frag_init(f, lane, wm, wn);
    float acc[4][8][4];

    // ---- q ----
#pragma unroll
    for (int mt = 0; mt < 4; mt++)
#pragma unroll
        for (int nt = 0; nt < 8; nt++)
#pragma unroll
            for (int e = 0; e < 4; e++) acc[mt][nt][e] = 0.f;
    cp_wait<1>();
    __syncthreads();
#pragma unroll
    for (int t = 0; t < 4; t++)
        compute_k32(Asb + t * SUB_BYTES, Bsb0 + t * SUB_BYTES, f, acc);
    __syncthreads();
    epilogue_half(acc, Cq, QKVROW, Bsb0, wm, wn, lane, tid);
    __syncthreads();
    // group 3: B(v) into buffer 0 (q stage fully drained by the sync above)
#pragma unroll
    for (int t = 0; t < 4; t++)
        load_sub(Bsb0 + t * SUB_BYTES, Bv + t * 32, BLKD);
    cp_commit();

    // ---- k ----
#pragma unroll
    for (int mt = 0; mt < 4; mt++)
#pragma unroll
        for (int nt = 0; nt < 8; nt++)
#pragma unroll
            for (int e = 0; e < 4; e++) acc[mt][nt][e] = 0.f;
    cp_wait<1>();
    __syncthreads();
#pragma unroll
    for (int t = 0; t < 4; t++)
        compute_k32(Asb + t * SUB_BYTES, Bsb1 + t * SUB_BYTES, f, acc);
    __syncthreads();
    epilogue_half(acc, Ck, QKVROW, Bsb1, wm, wn, lane, tid);

    // ---- v ----
#pragma unroll
    for (int mt = 0; mt < 4; mt++)
#pragma unroll
        for (int nt = 0; nt < 8; nt++)
#pragma unroll
            for (int e = 0; e < 4; e++) acc[mt][nt][e] = 0.f;
    cp_wait<0>();
    __syncthreads();
#pragma unroll
    for (int t = 0; t < 4; t++)
        compute_k32(Asb + t * SUB_BYTES, Bsb0 + t * SUB_BYTES, f, acc);
    __syncthreads();
    epilogue_half(acc, Cv, QKVROW, Bsb0, wm, wn, lane, tid);
}

// ---------------- output projection: K=768 as 12 k64 chunks, 2-stage ring ----------
// grid (32, 8), 128 threads, 64KB smem -> 2 CTAs/SM.
__global__ void __launch_bounds__(128, 2) gemm_f_kernel(float* __restrict__ out) {
    extern __shared__ __align__(16) char dsm[];
    char* base = (char*)(((uintptr_t)dsm + 1023) & ~(uintptr_t)1023);
    const uint32_t sb = s2u(base);

    const int tid  = threadIdx.x;
    const int lane = tid & 31;
    const int warp = tid >> 5;
    const int wm = warp & 1, wn = warp >> 1;
    const int gid = lane >> 2, tig = lane & 3;

    const int blk = blockIdx.y;
    const __half* A = g_att + (size_t)blockIdx.x * 128 * QKVROW + blk * INNER;
    const __half* B = g_wft + (size_t)blk * BLKD * INNER;
    float*        C = out + (size_t)blockIdx.x * 128 * DIMX + blk * BLKD;

#define LOAD_CHUNK(c, s)                                                           \
    do {                                                                           \
        const uint32_t st = sb + (uint32_t)(s) * (4 * SUB_BYTES);                  \
        load_sub(st,                 A + (c) * 64,      QKVROW);                   \
        load_sub(st + SUB_BYTES,     A + (c) * 64 + 32, QKVROW);                   \
        load_sub(st + 2 * SUB_BYTES, B + (c) * 64,      INNER);                    \
        load_sub(st + 3 * SUB_BYTES, B + (c) * 64 + 32, INNER);                    \
        cp_commit();                                                               \
    } while (0)

    FragCtx f;
    frag_init(f, lane, wm, wn);
    float acc[4][8][4];
#pragma unroll
    for (int mt = 0; mt < 4; mt++)
#pragma unroll
        for (int nt = 0; nt < 8; nt++)
#pragma unroll
            for (int e = 0; e < 4; e++) acc[mt][nt][e] = 0.f;

    LOAD_CHUNK(0, 0);

    for (int t = 0; t < 12; t++) {
        if (t + 1 < 12) { LOAD_CHUNK(t + 1, (t + 1) & 1); cp_wait<1>(); }
        else            { cp_wait<0>(); }
        __syncthreads();

        const uint32_t st = sb + (uint32_t)(t & 1) * (4 * SUB_BYTES);
        compute_k32(st,             st + 2 * SUB_BYTES, f, acc);
        compute_k32(st + SUB_BYTES, st + 3 * SUB_BYTES, f, acc);
        __syncthreads();
    }
#undef LOAD_CHUNK

    // staged fp32 epilogue: STS.64 -> rotated 64KB stage -> coalesced STG.128
#pragma unroll
    for (int mt = 0; mt < 4; mt++) {
#pragma unroll
        for (int nt = 0; nt < 8; nt++) {
            int r0  = wm * 64 + mt * 16 + gid;
            int u   = wn * 16 + nt * 2 + (tig >> 1);
            int off = (tig & 1) * 8;
            sts64(sb + FROT(r0, u) + off,     acc[mt][nt][0], acc[mt][nt][1]);
            sts64(sb + FROT(r0 + 8, u) + off, acc[mt][nt][2], acc[mt][nt][3]);
        }
    }
    __syncthreads();
#pragma unroll
    for (int p = 0; p < 32; p++) {
        int row = (tid >> 5) + p * 4;
        int u   = tid & 31;
        uint4 val;
        lds128(val, sb + FROT(row, u));
        *(uint4*)(C + (size_t)row * DIMX + u * 4) = val;
    }
}

// ---------------- attention: 1 CTA per token, 1 warp per head -----------------------
// scores via recursive-halving multireduce: 62 shuffles/warp instead of 320.
__global__ void __launch_bounds__(384) attn_kernel(float* __restrict__ smean) {
    const int t    = blockIdx.x;
    const int h    = threadIdx.x >> 5;
    const int lane = threadIdx.x & 31;

    __shared__ float sm[NHEAD][64];

    const size_t base = (size_t)t * QKVROW + h * HDIM;
    float2 q[8], k[8], v[8];
#pragma unroll
    for (int j = 0; j < 8; j++) {
        q[j] = __half22float2(((const __half2*)(g_q + base + j * INNER))[lane]);
        k[j] = __half22float2(((const __half2*)(g_k + base + j * INNER))[lane]);
        v[j] = __half22float2(((const __half2*)(g_v + base + j * INNER))[lane]);
    }

    // scores s(i,j) = dot64(q_i, k_j), f = i*8+j. Two passes of 32 sums each.
    // After 5 butterfly rounds, lane l holds pass-0 f=l (own0) and pass-1 f=l+32 (own1).
    float own0 = 0.f, own1 = 0.f;
#pragma unroll
    for (int hp = 0; hp < 2; hp++) {
        float cur[32];
#pragma unroll
        for (int fl = 0; fl < 32; fl++) {
            const int i = hp * 4 + (fl >> 3);
            const int j = fl & 7;
            cur[fl] = q[i].x * k[j].x + q[i].y * k[j].y;
        }
#pragma unroll
        for (int r = 0; r < 5; r++) {
            const int bit = (lane >> r) & 1;
#pragma unroll
            for (int x = 0; x < 16; x++) {
                if (x < (16 >> r)) {
                    float a0 = cur[2 * x], a1 = cur[2 * x + 1];
                    float keep = bit ? a1 : a0;
                    float send = bit ? a0 : a1;
                    float got = __shfl_xor_sync(0xFFFFFFFFu, send, 1 << r);
                    cur[x] = keep + got;
                }
            }
        }
        if (hp == 0) own0 = cur[0];
        else         own1 = cur[0];
    }
    own0 *= SCALE;
    own1 *= SCALE;

    // softmax over j within 8-lane groups
    float m0 = own0, m1 = own1;
#pragma unroll
    for (int m = 4; m >= 1; m >>= 1) {
        m0 = fmaxf(m0, __shfl_xor_sync(0xFFFFFFFFu, m0, m));
        m1 = fmaxf(m1, __shfl_xor_sync(0xFFFFFFFFu, m1, m));
    }
    float e0 = expf(own0 - m0), e1 = expf(own1 - m1);
    float s0 = e0, s1 = e1;
#pragma unroll
    for (int m = 4; m >= 1; m >>= 1) {
        s0 += __shfl_xor_sync(0xFFFFFFFFu, s0, m);
        s1 += __shfl_xor_sync(0xFFFFFFFFu, s1, m);
    }
    const float a0 = e0 / s0;
    const float a1 = e1 / s1;

    sm[h][lane]      = a0;
    sm[h][lane + 32] = a1;
    __syncwarp();

    // out_i = sum_j a(i,j) * v_j  (a via LDS broadcast)
    float2 acc[8];
#pragma unroll
    for (int i = 0; i < 8; i++) acc[i] = make_float2(0.f, 0.f);
#pragma unroll
    for (int i = 0; i < 8; i++) {
#pragma unroll
        for (int j = 0; j < 8; j++) {
            float aij = sm[h][i * 8 + j];
            acc[i].x = fmaf(aij, v[j].x, acc[i].x);
            acc[i].y = fmaf(aij, v[j].y, acc[i].y);
        }
    }
#pragma unroll
    for (int i = 0; i < 8; i++) {
        *(__half2*)(g_att + (size_t)t * QKVROW + i * INNER + h * HDIM + 2 * lane) =
            __floats2half2_rn(acc[i].x, acc[i].y);
    }

    __syncthreads();
    if (smean != nullptr && threadIdx.x < 64) {
        float s = 0.f;
#pragma unroll
        for (int hh = 0; hh < NHEAD; hh++) s += sm[hh][threadIdx.x];
        smean[(size_t)t * 64 + threadIdx.x] = s * (1.0f / 12.0f);
    }
}

// ---------------- launch ----------------
extern "C" void kernel_launch(void* const* d_in, const int* in_sizes, int n_in,
                              void* d_out, int out_size) {
    const float* x  = (const float*)d_in[0];
    const float* Wq = (const float*)d_in[1];
    const float* Wk = (const float*)d_in[2];
    const float* Wv = (const float*)d_in[3];
    const float* Wf = (const float*)d_in[4];
    float* out = (float*)d_out;

    cudaFuncSetAttribute(gemm_qkv_kernel, cudaFuncAttributeMaxDynamicSharedMemorySize, QKV_DSM);
    cudaFuncSetAttribute(gemm_f_kernel,   cudaFuncAttributeMaxDynamicSharedMemorySize, F_DSM);

    conv_x_kernel<<<SEQB * DIMX / 4 / 256, 256>>>(x);
    transpose_qkv_kernel<<<dim3(INNER / 32, BLKD / 32, 24), 256>>>(Wq, Wk, Wv);
    transpose_f_kernel<<<dim3(BLKD / 32, INNER / 32, NBLK), 256>>>(Wf);

    gemm_qkv_kernel<<<dim3(6, 32, 8), 128, QKV_DSM>>>();

    float* smean = (out_size >= SEQB * DIMX + SEQB * 64) ? (out + (size_t)SEQB * DIMX)
                                                         : nullptr;
    attn_kernel<<<SEQB, 384>>>(smean);

    gemm_f_kernel<<<dim3(32, NBLK), 128, F_DSM>>>(out);
}

// round 11
// speedup vs baseline: 2.4923x; 1.0118x over previous
#include <cuda_runtime.h>
#include <cuda_fp16.h>
#include <cstdint>

// Problem constants
#define SEQB   4096
#define DIMX   1024
#define NBLK   8
#define BLKD   128
#define NHEAD  12
#define HDIM   64
#define INNER  768
#define QKVROW (NBLK*INNER)        // 6144
#define WELEM  (NBLK*BLKD*INNER)   // 786432
#define SCALE  0.125f

// 128x32-half subtile (8KB), 64B rows, XOR-swizzled at 16B granularity
#define SUB_BYTES 8192
#define SWZ(row, ch) (((row) * 64) + ((((ch) ^ (((row) >> 1) & 3)) << 4)))

// fp32 epilogue stage layout (gemm_f)
#define FROT(row, u) (((row) * 512) + (((((u) + (row)) & 31)) << 4))   // fp32 tile, 64KB

#define QKV_DSM (12*SUB_BYTES + 1024)   // A(32KB) + 2 B buffers(64KB)
#define F_DSM   (8*SUB_BYTES + 1024)    // 2 stages x (2A + 2B); stage reuses all 64KB

// ---------------- scratch (device globals; allocation is forbidden) ----------------
__device__ __align__(16) __half g_xh [SEQB*DIMX];
__device__ __align__(16) __half g_wqt[WELEM];         // [blk][n=INNER][k=BLKD]
__device__ __align__(16) __half g_wkt[WELEM];
__device__ __align__(16) __half g_wvt[WELEM];
__device__ __align__(16) __half g_wft[WELEM];         // [blk][n=BLKD][k=INNER]
__device__ __align__(16) __half g_q  [SEQB*QKVROW];
__device__ __align__(16) __half g_k  [SEQB*QKVROW];
__device__ __align__(16) __half g_v  [SEQB*QKVROW];
__device__ __align__(16) __half g_att[SEQB*QKVROW];

// ---------------- helpers ----------------
__device__ __forceinline__ void mma_f16(float c[4], const uint32_t a[4],
                                        uint32_t b0, uint32_t b1) {
    asm volatile(
        "mma.sync.aligned.m16n8k16.row.col.f32.f16.f16.f32 "
        "{%0,%1,%2,%3}, {%4,%5,%6,%7}, {%8,%9}, {%0,%1,%2,%3};\n"
        : "+f"(c[0]), "+f"(c[1]), "+f"(c[2]), "+f"(c[3])
        : "r"(a[0]), "r"(a[1]), "r"(a[2]), "r"(a[3]), "r"(b0), "r"(b1));
}

__device__ __forceinline__ void ldsm4(uint32_t r[4], uint32_t addr) {
    asm volatile("ldmatrix.sync.aligned.m8n8.x4.shared.b16 {%0,%1,%2,%3}, [%4];"
                 : "=r"(r[0]), "=r"(r[1]), "=r"(r[2]), "=r"(r[3]) : "r"(addr));
}

__device__ __forceinline__ void stsm4(uint32_t addr, uint32_t v0, uint32_t v1,
                                      uint32_t v2, uint32_t v3) {
    asm volatile("stmatrix.sync.aligned.m8n8.x4.shared.b16 [%0], {%1,%2,%3,%4};"
                 :: "r"(addr), "r"(v0), "r"(v1), "r"(v2), "r"(v3) : "memory");
}

__device__ __forceinline__ void lds128(uint4& v, uint32_t addr) {
    asm volatile("ld.shared.v4.u32 {%0,%1,%2,%3}, [%4];"
                 : "=r"(v.x), "=r"(v.y), "=r"(v.z), "=r"(v.w) : "r"(addr));
}

__device__ __forceinline__ void sts64(uint32_t addr, float a, float b) {
    asm volatile("st.shared.v2.f32 [%0], {%1,%2};" :: "r"(addr), "f"(a), "f"(b) : "memory");
}

__device__ __forceinline__ uint32_t pack_h2(float a, float b) {
    __half2 h = __floats2half2_rn(a, b);
    return *(uint32_t*)&h;
}

__device__ __forceinline__ void cpa16(uint32_t smem_dst, const __half* gmem_src) {
    asm volatile("cp.async.ca.shared.global [%0], [%1], 16;\n" :: "r"(smem_dst), "l"(gmem_src));
}
__device__ __forceinline__ void cp_commit() { asm volatile("cp.async.commit_group;\n"); }
template <int N>
__device__ __forceinline__ void cp_wait() { asm volatile("cp.async.wait_group %0;\n" :: "n"(N)); }

__device__ __forceinline__ uint32_t s2u(const void* p) {
    return (uint32_t)__cvta_generic_to_shared(p);
}

// ---------------- prep: x -> half ----------------
__global__ void conv_x_kernel(const float* __restrict__ x) {
    int i = (blockIdx.x * blockDim.x + threadIdx.x) * 4;
    float4 v = *(const float4*)(x + i);
    __half2* o = (__half2*)(g_xh + i);
    o[0] = __floats2half2_rn(v.x, v.y);
    o[1] = __floats2half2_rn(v.z, v.w);
}

// ---------------- prep: transpose weights to [blk][n][k] half ----------------
__global__ void transpose_qkv_kernel(const float* __restrict__ wq,
                                     const float* __restrict__ wk,
                                     const float* __restrict__ wv) {
    __shared__ float tile[32][33];
    const int mat = blockIdx.z >> 3;
    const int blk = blockIdx.z & 7;
    const float* W = (mat == 0) ? wq : (mat == 1) ? wk : wv;
    __half* O      = (mat == 0) ? g_wqt : (mat == 1) ? g_wkt : g_wvt;
    const float* Wb = W + (size_t)blk * BLKD * INNER;   // [k=BLKD][n=INNER]
    __half* Ob      = O + (size_t)blk * BLKD * INNER;   // [n=INNER][k=BLKD]
    int n0 = blockIdx.x * 32, k0 = blockIdx.y * 32;
    int tx = threadIdx.x & 31, ty0 = threadIdx.x >> 5;
#pragma unroll
    for (int p = 0; p < 4; p++) {
        int ty = ty0 + p * 8;
        tile[ty][tx] = Wb[(size_t)(k0 + ty) * INNER + n0 + tx];
    }
    __syncthreads();
#pragma unroll
    for (int p = 0; p < 4; p++) {
        int ty = ty0 + p * 8;
        Ob[(size_t)(n0 + ty) * BLKD + k0 + tx] = __float2half_rn(tile[tx][ty]);
    }
}

__global__ void transpose_f_kernel(const float* __restrict__ wf) {
    __shared__ float tile[32][33];
    const int blk = blockIdx.z;
    const float* Wb = wf + (size_t)blk * INNER * BLKD;    // [k=INNER][n=BLKD]
    __half* Ob      = g_wft + (size_t)blk * INNER * BLKD; // [n=BLKD][k=INNER]
    int n0 = blockIdx.x * 32, k0 = blockIdx.y * 32;
    int tx = threadIdx.x & 31, ty0 = threadIdx.x >> 5;
#pragma unroll
    for (int p = 0; p < 4; p++) {
        int ty = ty0 + p * 8;
        tile[ty][tx] = Wb[(size_t)(k0 + ty) * BLKD + n0 + tx];
    }
    __syncthreads();
#pragma unroll
    for (int p = 0; p < 4; p++) {
        int ty = ty0 + p * 8;
        Ob[(size_t)(n0 + ty) * INNER + k0 + tx] = __float2half_rn(tile[tx][ty]);
    }
}

// ---------------- mma core: warp tile 64(M) x 64(N), CTA 128x128, 4 warps ---------
struct FragCtx {
    int a_row[4];
    int b_row[4];
    int ac, bc;
};

__device__ __forceinline__ void frag_init(FragCtx& f, int lane, int wm, int wn) {
#pragma unroll
    for (int mt = 0; mt < 4; mt++)
        f.a_row[mt] = wm * 64 + mt * 16 + (lane & 7) + ((lane >> 3) & 1) * 8;
#pragma unroll
    for (int np = 0; np < 4; np++)
        f.b_row[np] = wn * 64 + np * 16 + (lane & 7) + ((lane >> 4) & 1) * 8;
    f.ac = lane >> 4;
    f.bc = (lane >> 3) & 1;
}

__device__ __forceinline__ void compute_k32(uint32_t ab, uint32_t bb, const FragCtx& f,
                                            float acc[4][8][4]) {
#pragma unroll
    for (int ks = 0; ks < 2; ks++) {
        const int kb = ks * 2;
        uint32_t a[4][4];
#pragma unroll
        for (int mt = 0; mt < 4; mt++)
            ldsm4(a[mt], ab + SWZ(f.a_row[mt], kb + f.ac));
        uint32_t bf[4][4];
#pragma unroll
        for (int np = 0; np < 4; np++)
            ldsm4(bf[np], bb + SWZ(f.b_row[np], kb + f.bc));
#pragma unroll
        for (int mt = 0; mt < 4; mt++) {
#pragma unroll
            for (int np = 0; np < 4; np++) {
                mma_f16(acc[mt][np * 2 + 0], a[mt], bf[np][0], bf[np][1]);
                mma_f16(acc[mt][np * 2 + 1], a[mt], bf[np][2], bf[np][3]);
            }
        }
    }
}

// load one 128x32 subtile (row-major src, row stride ld halves); 128 threads, 4 cp each
__device__ __forceinline__ void load_sub(uint32_t dst, const __half* __restrict__ src, int ld) {
    const int r0 = threadIdx.x >> 2, c = threadIdx.x & 3;
#pragma unroll
    for (int p = 0; p < 4; p++) {
        const int r = r0 + p * 32;
        cpa16(dst + SWZ(r, c), src + (size_t)r * ld + c * 8);
    }
}

// warp-local subtile load: one warp covers a whole 128x32 subtile (16 cp per lane)
__device__ __forceinline__ void load_sub_warp(uint32_t dst, const __half* __restrict__ src,
                                              int ld, int lane) {
    const int r0 = lane >> 2, c = lane & 3;
#pragma unroll
    for (int p = 0; p < 16; p++) {
        const int r = r0 + p * 8;
        cpa16(dst + SWZ(r, c), src + (size_t)r * ld + c * 8);
    }
}

// ---------------- per-warp half epilogue: stmatrix -> own 8KB region -> STG.128 ----
// Warp quadrant 64x64 halves = 8KB. Region rows: 64 x 128B, 16B units rotated by row.
__device__ __forceinline__ void warp_epi_half(const float acc[4][8][4],
                                              __half* __restrict__ C, int ldc,
                                              uint32_t region, int wm, int wn, int lane) {
    const int t4 = lane >> 3, rr = lane & 7;
#pragma unroll
    for (int mt = 0; mt < 4; mt++) {
#pragma unroll
        for (int ntp = 0; ntp < 4; ntp++) {
            int lr = mt * 16 + (t4 & 1) * 8 + rr;
            int u  = ntp * 2 + (t4 >> 1);
            uint32_t v0 = pack_h2(acc[mt][2 * ntp][0],     acc[mt][2 * ntp][1]);
            uint32_t v1 = pack_h2(acc[mt][2 * ntp][2],     acc[mt][2 * ntp][3]);
            uint32_t v2 = pack_h2(acc[mt][2 * ntp + 1][0], acc[mt][2 * ntp + 1][1]);
            uint32_t v3 = pack_h2(acc[mt][2 * ntp + 1][2], acc[mt][2 * ntp + 1][3]);
            stsm4(region + lr * 128 + (((u + lr) & 7) << 4), v0, v1, v2, v3);
        }
    }
    __syncwarp();
#pragma unroll
    for (int p = 0; p < 16; p++) {
        int lr = p * 4 + (lane >> 3);
        int u  = lane & 7;
        uint4 val;
        lds128(val, region + lr * 128 + (((u + lr) & 7) << 4));
        *(uint4*)(C + (size_t)(wm * 64 + lr) * ldc + wn * 64 + u * 8) = val;
    }
}

// ---------------- QKV: fused q/k/v, per-warp epilogues. grid (6, 32, 8) ------------
__global__ void __launch_bounds__(128, 2) gemm_qkv_kernel() {
    extern __shared__ __align__(16) char dsm[];
    char* base = (char*)(((uintptr_t)dsm + 1023) & ~(uintptr_t)1023);
    const uint32_t Asb = s2u(base);
    const uint32_t Bsb0 = Asb + 4 * SUB_BYTES;
    const uint32_t Bsb1 = Asb + 8 * SUB_BYTES;

    const int tid  = threadIdx.x;
    const int lane = tid & 31;
    const int warp = tid >> 5;
    const int wm = warp & 1, wn = warp >> 1;

    const int blk = blockIdx.z;
    const size_t woff = (size_t)blk * BLKD * INNER + (size_t)blockIdx.x * 128 * BLKD;
    const size_t coff = (size_t)blockIdx.y * 128 * QKVROW + blk * INNER + blockIdx.x * 128;
    const __half* A  = g_xh + (size_t)blockIdx.y * 128 * DIMX + blk * BLKD;
    const __half* Bq = g_wqt + woff;
    const __half* Bk = g_wkt + woff;
    const __half* Bv = g_wvt + woff;
    __half* Cq = g_q + coff;
    __half* Ck = g_k + coff;
    __half* Cv = g_v + coff;

    const uint32_t reg0 = Bsb0 + (uint32_t)warp * SUB_BYTES;   // warp's stage in B0
    const uint32_t reg1 = Bsb1 + (uint32_t)warp * SUB_BYTES;   // warp's stage in B1

    // group1: A + B(q); group2: B(k)
#pragma unroll
    for (int t = 0; t < 4; t++) {
        load_sub(Asb + t * SUB_BYTES,  A  + t * 32, DIMX);
        load_sub(Bsb0 + t * SUB_BYTES, Bq + t * 32, BLKD);
    }
    cp_commit();
#pragma unroll
    for (int t = 0; t < 4; t++)
        load_sub(Bsb1 + t * SUB_BYTES, Bk + t * 32, BLKD);
    cp_commit();

    FragCtx f;
    frag_init(f, lane, wm, wn);
    float acc[4][8][4];

    // ---- q ----
#pragma unroll
    for (int mt = 0; mt < 4; mt++)
#pragma unroll
        for (int nt = 0; nt < 8; nt++)
#pragma unroll
            for (int e = 0; e < 4; e++) acc[mt][nt][e] = 0.f;
    cp_wait<1>();           // group1 (A, Bq) complete
    __syncthreads();
#pragma unroll
    for (int t = 0; t < 4; t++)
        compute_k32(Asb + t * SUB_BYTES, Bsb0 + t * SUB_BYTES, f, acc);
    __syncthreads();        // all warps done reading B0 -> B0 usable as stage
    warp_epi_half(acc, Cq, QKVROW, reg0, wm, wn, lane);
    // group3: warp refills ITS OWN drained region with its Bv subtile (program order
    // after the region's LDS reads; cp.async data lands >=L2 latency later).
    load_sub_warp(reg0, Bv + warp * 32, BLKD, lane);
    cp_commit();

    // ---- k ----
#pragma unroll
    for (int mt = 0; mt < 4; mt++)
#pragma unroll
        for (int nt = 0; nt < 8; nt++)
#pragma unroll
            for (int e = 0; e < 4; e++) acc[mt][nt][e] = 0.f;
    cp_wait<1>();           // group2 (Bk) complete; own Bv may still be in flight
    __syncthreads();
#pragma unroll
    for (int t = 0; t < 4; t++)
        compute_k32(Asb + t * SUB_BYTES, Bsb1 + t * SUB_BYTES, f, acc);
    __syncthreads();        // all warps done reading B1 -> B1 usable as stage
    warp_epi_half(acc, Ck, QKVROW, reg1, wm, wn, lane);

    // ---- v ----
#pragma unroll
    for (int mt = 0; mt < 4; mt++)
#pragma unroll
        for (int nt = 0; nt < 8; nt++)
#pragma unroll
            for (int e = 0; e < 4; e++) acc[mt][nt][e] = 0.f;
    cp_wait<0>();           // all Bv subtiles (every thread's groups) complete
    __syncthreads();
#pragma unroll
    for (int t = 0; t < 4; t++)
        compute_k32(Asb + t * SUB_BYTES, Bsb0 + t * SUB_BYTES, f, acc);
    // stage v into warp's own B1 region: last touched by this warp's own k drain,
    // and no other warp accesses it after the pre-v __syncthreads.
    warp_epi_half(acc, Cv, QKVROW, reg1, wm, wn, lane);
}

// ---------------- output projection: K=768 as 12 k64 chunks, 2-stage ring ----------
// grid (32, 8), 128 threads, 64KB smem -> 2 CTAs/SM.
__global__ void __launch_bounds__(128, 2) gemm_f_kernel(float* __restrict__ out) {
    extern __shared__ __align__(16) char dsm[];
    char* base = (char*)(((uintptr_t)dsm + 1023) & ~(uintptr_t)1023);
    const uint32_t sb = s2u(base);

    const int tid  = threadIdx.x;
    const int lane = tid & 31;
    const int warp = tid >> 5;
    const int wm = warp & 1, wn = warp >> 1;
    const int gid = lane >> 2, tig = lane & 3;

    const int blk = blockIdx.y;
    const __half* A = g_att + (size_t)blockIdx.x * 128 * QKVROW + blk * INNER;
    const __half* B = g_wft + (size_t)blk * BLKD * INNER;
    float*        C = out + (size_t)blockIdx.x * 128 * DIMX + blk * BLKD;

#define LOAD_CHUNK(c, s)                                                           \
    do {                                                                           \
        const uint32_t st = sb + (uint32_t)(s) * (4 * SUB_BYTES);                  \
        load_sub(st,                 A + (c) * 64,      QKVROW);                   \
        load_sub(st + SUB_BYTES,     A + (c) * 64 + 32, QKVROW);                   \
        load_sub(st + 2 * SUB_BYTES, B + (c) * 64,      INNER);                    \
        load_sub(st + 3 * SUB_BYTES, B + (c) * 64 + 32, INNER);                    \
        cp_commit();                                                               \
    } while (0)

    FragCtx f;
    frag_init(f, lane, wm, wn);
    float acc[4][8][4];
#pragma unroll
    for (int mt = 0; mt < 4; mt++)
#pragma unroll
        for (int nt = 0; nt < 8; nt++)
#pragma unroll
            for (int e = 0; e < 4; e++) acc[mt][nt][e] = 0.f;

    LOAD_CHUNK(0, 0);

    for (int t = 0; t < 12; t++) {
        if (t + 1 < 12) { LOAD_CHUNK(t + 1, (t + 1) & 1); cp_wait<1>(); }
        else            { cp_wait<0>(); }
        __syncthreads();

        const uint32_t st = sb + (uint32_t)(t & 1) * (4 * SUB_BYTES);
        compute_k32(st,             st + 2 * SUB_BYTES, f, acc);
        compute_k32(st + SUB_BYTES, st + 3 * SUB_BYTES, f, acc);
        __syncthreads();
    }
#undef LOAD_CHUNK

    // staged fp32 epilogue: STS.64 -> rotated 64KB stage -> coalesced STG.128
#pragma unroll
    for (int mt = 0; mt < 4; mt++) {
#pragma unroll
        for (int nt = 0; nt < 8; nt++) {
            int r0  = wm * 64 + mt * 16 + gid;
            int u   = wn * 16 + nt * 2 + (tig >> 1);
            int off = (tig & 1) * 8;
            sts64(sb + FROT(r0, u) + off,     acc[mt][nt][0], acc[mt][nt][1]);
            sts64(sb + FROT(r0 + 8, u) + off, acc[mt][nt][2], acc[mt][nt][3]);
        }
    }
    __syncthreads();
#pragma unroll
    for (int p = 0; p < 32; p++) {
        int row = (tid >> 5) + p * 4;
        int u   = tid & 31;
        uint4 val;
        lds128(val, sb + FROT(row, u));
        *(uint4*)(C + (size_t)row * DIMX + u * 4) = val;
    }
}

// ---------------- attention: 1 CTA per token, 1 warp per head -----------------------
// scores via recursive-halving multireduce: 62 shuffles/warp instead of 320.
__global__ void __launch_bounds__(384) attn_kernel(float* __restrict__ smean) {
    const int t    = blockIdx.x;
    const int h    = threadIdx.x >> 5;
    const int lane = threadIdx.x & 31;

    __shared__ float sm[NHEAD][64];

    const size_t base = (size_t)t * QKVROW + h * HDIM;
    float2 q[8], k[8], v[8];
#pragma unroll
    for (int j = 0; j < 8; j++) {
        q[j] = __half22float2(((const __half2*)(g_q + base + j * INNER))[lane]);
        k[j] = __half22float2(((const __half2*)(g_k + base + j * INNER))[lane]);
        v[j] = __half22float2(((const __half2*)(g_v + base + j * INNER))[lane]);
    }

    // scores s(i,j) = dot64(q_i, k_j), f = i*8+j. Two passes of 32 sums each.
    float own0 = 0.f, own1 = 0.f;
#pragma unroll
    for (int hp = 0; hp < 2; hp++) {
        float cur[32];
#pragma unroll
        for (int fl = 0; fl < 32; fl++) {
            const int i = hp * 4 + (fl >> 3);
            const int j = fl & 7;
            cur[fl] = q[i].x * k[j].x + q[i].y * k[j].y;
        }
#pragma unroll
        for (int r = 0; r < 5; r++) {
            const int bit = (lane >> r) & 1;
#pragma unroll
            for (int x = 0; x < 16; x++) {
                if (x < (16 >> r)) {
                    float a0 = cur[2 * x], a1 = cur[2 * x + 1];
                    float keep = bit ? a1 : a0;
                    float send = bit ? a0 : a1;
                    float got = __shfl_xor_sync(0xFFFFFFFFu, send, 1 << r);
                    cur[x] = keep + got;
                }
            }
        }
        if (hp == 0) own0 = cur[0];
        else         own1 = cur[0];
    }
    own0 *= SCALE;
    own1 *= SCALE;

    // softmax over j within 8-lane groups
    float m0 = own0, m1 = own1;
#pragma unroll
    for (int m = 4; m >= 1; m >>= 1) {
        m0 = fmaxf(m0, __shfl_xor_sync(0xFFFFFFFFu, m0, m));
        m1 = fmaxf(m1, __shfl_xor_sync(0xFFFFFFFFu, m1, m));
    }
    float e0 = expf(own0 - m0), e1 = expf(own1 - m1);
    float s0 = e0, s1 = e1;
#pragma unroll
    for (int m = 4; m >= 1; m >>= 1) {
        s0 += __shfl_xor_sync(0xFFFFFFFFu, s0, m);
        s1 += __shfl_xor_sync(0xFFFFFFFFu, s1, m);
    }
    const float a0 = e0 / s0;
    const float a1 = e1 / s1;

    sm[h][lane]      = a0;
    sm[h][lane + 32] = a1;
    __syncwarp();

    // out_i = sum_j a(i,j) * v_j  (a via LDS broadcast)
    float2 acc[8];
#pragma unroll
    for (int i = 0; i < 8; i++) acc[i] = make_float2(0.f, 0.f);
#pragma unroll
    for (int i = 0; i < 8; i++) {
#pragma unroll
        for (int j = 0; j < 8; j++) {
            float aij = sm[h][i * 8 + j];
            acc[i].x = fmaf(aij, v[j].x, acc[i].x);
            acc[i].y = fmaf(aij, v[j].y, acc[i].y);
        }
    }
#pragma unroll
    for (int i = 0; i < 8; i++) {
        *(__half2*)(g_att + (size_t)t * QKVROW + i * INNER + h * HDIM + 2 * lane) =
            __floats2half2_rn(acc[i].x, acc[i].y);
    }

    __syncthreads();
    if (smean != nullptr && threadIdx.x < 64) {
        float s = 0.f;
#pragma unroll
        for (int hh = 0; hh < NHEAD; hh++) s += sm[hh][threadIdx.x];
        smean[(size_t)t * 64 + threadIdx.x] = s * (1.0f / 12.0f);
    }
}

// ---------------- launch ----------------
extern "C" void kernel_launch(void* const* d_in, const int* in_sizes, int n_in,
                              void* d_out, int out_size) {
    const float* x  = (const float*)d_in[0];
    const float* Wq = (const float*)d_in[1];
    const float* Wk = (const float*)d_in[2];
    const float* Wv = (const float*)d_in[3];
    const float* Wf = (const float*)d_in[4];
    float* out = (float*)d_out;

    cudaFuncSetAttribute(gemm_qkv_kernel, cudaFuncAttributeMaxDynamicSharedMemorySize, QKV_DSM);
    cudaFuncSetAttribute(gemm_f_kernel,   cudaFuncAttributeMaxDynamicSharedMemorySize, F_DSM);

    conv_x_kernel<<<SEQB * DIMX / 4 / 256, 256>>>(x);
    transpose_qkv_kernel<<<dim3(INNER / 32, BLKD / 32, 24), 256>>>(Wq, Wk, Wv);
    transpose_f_kernel<<<dim3(BLKD / 32, INNER / 32, NBLK), 256>>>(Wf);

    gemm_qkv_kernel<<<dim3(6, 32, 8), 128, QKV_DSM>>>();

    float* smean = (out_size >= SEQB * DIMX + SEQB * 64) ? (out + (size_t)SEQB * DIMX)
                                                         : nullptr;
    attn_kernel<<<SEQB, 384>>>(smean);

    gemm_f_kernel<<<dim3(32, NBLK), 128, F_DSM>>>(out);
}